// round 2
// baseline (speedup 1.0000x reference)
#include <cuda_runtime.h>
#include <math.h>

#define Bsz 4
#define Cc 512
#define MID 256
#define CMn 76
#define Hh 128
#define Ww 128
#define HW 16384
#define Pp 1024
#define Np 16

// ---------------- static scratch (no allocation allowed) ----------------
__device__ float g_pool[Bsz * CMn * Np];           // [b][cm][n]
__device__ float g_smx[(size_t)Bsz * Np * CMn * Pp];   // softmax(sim) [bn][cm][p]
__device__ float g_local[(size_t)Bsz * Np * CMn * Cc]; // [bn][cm][k]
__device__ float g_kk[(size_t)Bsz * Np * CMn * MID];   // k proj [bn][cm][m]
__device__ float g_vv[CMn * MID];                      // v proj [cm][m]
__device__ float g_q[(size_t)Bsz * HW * MID];          // q [b*HW + pix][m]
__device__ float g_o[(size_t)Bsz * HW * MID];          // attention out [b*HW + pix][m]

// ---------------- 1. adaptive avg pool (patch means) ----------------
// grid 4864 = (b*CM)*16, block 256
__global__ void k_pool(const float* __restrict__ sim, float* __restrict__ out_tail) {
    int id = blockIdx.x;          // (b*CM + cm)*16 + n
    int n  = id & 15;
    int bc = id >> 4;             // b*CM + cm
    int i0 = (n >> 2) * 32, j0 = (n & 3) * 32;
    const float* base = sim + (size_t)bc * HW;
    float s = 0.f;
    for (int p = threadIdx.x; p < 1024; p += 256) {
        int pi = p >> 5, pj = p & 31;
        s += base[(i0 + pi) * Ww + j0 + pj];
    }
    __shared__ float red[256];
    red[threadIdx.x] = s; __syncthreads();
    for (int o = 128; o > 0; o >>= 1) {
        if (threadIdx.x < o) red[threadIdx.x] += red[threadIdx.x + o];
        __syncthreads();
    }
    if (threadIdx.x == 0) {
        float m = red[0] * (1.0f / 1024.0f);
        g_pool[id]   = m;
        out_tail[id] = m;
    }
}

// ---------------- 2. softmax of sim over pixels within patch ----------------
// grid 4864 = bn*CM + cm, block 256
__global__ void k_softmax(const float* __restrict__ sim) {
    int id = blockIdx.x;
    int cm = id % CMn;
    int bn = id / CMn;
    int n = bn & 15, b = bn >> 4;
    int i0 = (n >> 2) * 32, j0 = (n & 3) * 32;
    const float* base = sim + ((size_t)b * CMn + cm) * HW;
    int t = threadIdx.x;
    float v[4];
    float mx = -1e30f;
#pragma unroll
    for (int it = 0; it < 4; it++) {
        int p = t + it * 256;
        int pi = p >> 5, pj = p & 31;
        v[it] = base[(i0 + pi) * Ww + j0 + pj];
        mx = fmaxf(mx, v[it]);
    }
    __shared__ float red[256];
    red[t] = mx; __syncthreads();
    for (int o = 128; o > 0; o >>= 1) {
        if (t < o) red[t] = fmaxf(red[t], red[t + o]);
        __syncthreads();
    }
    float gmx = red[0]; __syncthreads();
    float s = 0.f;
#pragma unroll
    for (int it = 0; it < 4; it++) { v[it] = expf(v[it] - gmx); s += v[it]; }
    red[t] = s; __syncthreads();
    for (int o = 128; o > 0; o >>= 1) {
        if (t < o) red[t] += red[t + o];
        __syncthreads();
    }
    float inv = 1.0f / red[0];
    float* dst = g_smx + ((size_t)bn * CMn + cm) * Pp;
#pragma unroll
    for (int it = 0; it < 4; it++) { int p = t + it * 256; dst[p] = v[it] * inv; }
}

// ---------------- 3. local = (softmax sm)^T @ xs * conf ----------------
// per (b,n): [76 x 1024] x [1024 x 512] (NT, both p-contiguous)
// grid (8 nTile, 3 mTile, 64 bn), block (16,16), tile 32x64, per-thread 2x4
__global__ void k_local(const float* __restrict__ x) {
    int bn = blockIdx.z;
    int b = bn >> 4, n = bn & 15;
    int i0 = (n >> 2) * 32, j0 = (n & 3) * 32;
    int mBase = blockIdx.y * 32;   // cm
    int nBase = blockIdx.x * 64;   // channel k
    __shared__ float As[32][17];
    __shared__ float Bs[64][17];
    const float* Arow = g_smx + (size_t)bn * CMn * Pp;
    const float* xb = x + (size_t)b * Cc * HW;
    int tx = threadIdx.x, ty = threadIdx.y, tid = ty * 16 + tx;
    float acc[2][4] = {};
    for (int p0 = 0; p0 < 1024; p0 += 16) {
        int pi = p0 >> 5;
        int pjB = p0 & 31;
#pragma unroll
        for (int e = tid; e < 512; e += 256) {
            int r = e >> 4, pp = e & 15;
            int c = mBase + r;
            As[r][pp] = (c < CMn) ? Arow[(size_t)c * Pp + p0 + pp] : 0.f;
        }
#pragma unroll
        for (int e = tid; e < 1024; e += 256) {
            int r = e >> 4, pp = e & 15;
            int k = nBase + r;
            Bs[r][pp] = xb[(size_t)k * HW + (i0 + pi) * Ww + j0 + pjB + pp];
        }
        __syncthreads();
#pragma unroll
        for (int pp = 0; pp < 16; pp++) {
            float a0 = As[ty][pp], a1 = As[ty + 16][pp];
            float b0 = Bs[tx][pp], b1 = Bs[tx + 16][pp];
            float b2 = Bs[tx + 32][pp], b3 = Bs[tx + 48][pp];
            acc[0][0] += a0 * b0; acc[0][1] += a0 * b1; acc[0][2] += a0 * b2; acc[0][3] += a0 * b3;
            acc[1][0] += a1 * b0; acc[1][1] += a1 * b1; acc[1][2] += a1 * b2; acc[1][3] += a1 * b3;
        }
        __syncthreads();
    }
#pragma unroll
    for (int i = 0; i < 2; i++) {
        int c = mBase + ty + i * 16;
        if (c < CMn) {
            float conf = g_pool[(b * CMn + c) * 16 + n];
            float* dst = g_local + ((size_t)bn * CMn + c) * Cc;
#pragma unroll
            for (int j = 0; j < 4; j++) {
                int k = nBase + tx + j * 16;
                dst[k] = acc[i][j] * conf;
            }
        }
    }
}

// ---------------- 4. k = local @ Wk + bk ----------------
// per (b,n): [76 x 512] x [512 x 256]; grid (4,3,64), block (16,16), tile 32x64
__global__ void k_kproj(const float* __restrict__ Wk, const float* __restrict__ bk) {
    int bn = blockIdx.z;
    int mBase = blockIdx.y * 32;
    int nBase = blockIdx.x * 64;
    __shared__ float As[32][17];
    __shared__ float Bs[16][65];
    const float* Ap = g_local + (size_t)bn * CMn * Cc;
    int tx = threadIdx.x, ty = threadIdx.y, tid = ty * 16 + tx;
    float acc[2][4] = {};
    for (int k0 = 0; k0 < 512; k0 += 16) {
#pragma unroll
        for (int e = tid; e < 512; e += 256) {
            int r = e >> 4, kk = e & 15;
            int c = mBase + r;
            As[r][kk] = (c < CMn) ? Ap[(size_t)c * Cc + k0 + kk] : 0.f;
        }
#pragma unroll
        for (int e = tid; e < 1024; e += 256) {
            int kk = e >> 6, nn = e & 63;
            Bs[kk][nn] = Wk[(k0 + kk) * MID + nBase + nn];
        }
        __syncthreads();
#pragma unroll
        for (int kk = 0; kk < 16; kk++) {
            float a0 = As[ty][kk], a1 = As[ty + 16][kk];
#pragma unroll
            for (int j = 0; j < 4; j++) {
                float bb = Bs[kk][tx + j * 16];
                acc[0][j] += a0 * bb;
                acc[1][j] += a1 * bb;
            }
        }
        __syncthreads();
    }
#pragma unroll
    for (int i = 0; i < 2; i++) {
        int c = mBase + ty + i * 16;
        if (c < CMn) {
            float* dst = g_kk + ((size_t)bn * CMn + c) * MID;
#pragma unroll
            for (int j = 0; j < 4; j++) {
                int nn = nBase + tx + j * 16;
                dst[nn] = acc[i][j] + bk[nn];
            }
        }
    }
}

// ---------------- 5. v = g @ Wv + bv  (tiny) ----------------
// grid 76, block 256
__global__ void k_v(const float* __restrict__ g, const float* __restrict__ Wv,
                    const float* __restrict__ bv) {
    __shared__ float sg[512];
    int c = blockIdx.x, t = threadIdx.x;
    for (int k = t; k < 512; k += 256) sg[k] = g[c * 512 + k];
    __syncthreads();
    float acc = 0.f;
    for (int k = 0; k < 512; k++) acc += sg[k] * Wv[k * MID + t];
    g_vv[c * MID + t] = acc + bv[t];
}

// ---------------- 6. q = x^T @ Wq + bq ----------------
// per b: [16384 x 512] x [512 x 256]; grid (4, 256, 4), block (16,16), tile 64x64
__global__ void k_q(const float* __restrict__ x, const float* __restrict__ Wq,
                    const float* __restrict__ bq) {
    int b = blockIdx.z;
    int mBase = blockIdx.y * 64;   // pixel
    int nBase = blockIdx.x * 64;   // mid
    __shared__ float As[64][17];
    __shared__ float Bs[16][65];
    const float* xb = x + (size_t)b * Cc * HW;
    int tx = threadIdx.x, ty = threadIdx.y, tid = ty * 16 + tx;
    float acc[4][4] = {};
    for (int k0 = 0; k0 < 512; k0 += 16) {
#pragma unroll
        for (int e = tid; e < 1024; e += 256) {
            int kk = e >> 6, m = e & 63;
            As[m][kk] = xb[(size_t)(k0 + kk) * HW + mBase + m];
        }
#pragma unroll
        for (int e = tid; e < 1024; e += 256) {
            int kk = e >> 6, nn = e & 63;
            Bs[kk][nn] = Wq[(k0 + kk) * MID + nBase + nn];
        }
        __syncthreads();
#pragma unroll
        for (int kk = 0; kk < 16; kk++) {
            float a[4], bb[4];
#pragma unroll
            for (int i = 0; i < 4; i++) a[i] = As[ty + i * 16][kk];
#pragma unroll
            for (int j = 0; j < 4; j++) bb[j] = Bs[kk][tx + j * 16];
#pragma unroll
            for (int i = 0; i < 4; i++)
#pragma unroll
                for (int j = 0; j < 4; j++) acc[i][j] += a[i] * bb[j];
        }
        __syncthreads();
    }
#pragma unroll
    for (int i = 0; i < 4; i++) {
        int m = mBase + ty + i * 16;
        float* dst = g_q + ((size_t)b * HW + m) * MID;
#pragma unroll
        for (int j = 0; j < 4; j++) {
            int nn = nBase + tx + j * 16;
            dst[nn] = acc[i][j] + bq[nn];
        }
    }
}

// ---------------- 7. fused attention: logits -> softmax -> @v ----------------
// grid 2048 = bn*32 (one 32-pixel row chunk per block), block 256
__global__ void k_att() {
    __shared__ float qs[256][33];   // [m][p]
    __shared__ float ls[32][81];    // [p][c]
    int id = blockIdx.x;
    int pi = id & 31;        // pixel row within patch
    int bn = id >> 5;
    int b = bn >> 4, n = bn & 15;
    int i0 = (n >> 2) * 32, j0 = (n & 3) * 32;
    int row = i0 + pi;
    int t = threadIdx.x;

    const float* qbase = g_q + ((size_t)b * HW + row * Ww + j0) * MID;
#pragma unroll
    for (int e = t; e < 8192; e += 256) {
        int p = e >> 8, m = e & 255;
        qs[m][p] = qbase[(size_t)p * MID + m];
    }
    __syncthreads();

    const float* kbase = g_kk + (size_t)bn * CMn * MID;
    for (int idx = t; idx < 32 * CMn; idx += 256) {
        int p = idx & 31, c = idx >> 5;
        const float4* k4 = (const float4*)(kbase + c * MID);
        float s = 0.f;
#pragma unroll 8
        for (int m4 = 0; m4 < 64; m4++) {
            float4 kv = k4[m4];
            s += qs[m4 * 4 + 0][p] * kv.x + qs[m4 * 4 + 1][p] * kv.y
               + qs[m4 * 4 + 2][p] * kv.z + qs[m4 * 4 + 3][p] * kv.w;
        }
        ls[p][c] = s;
    }
    __syncthreads();

    // softmax over c (76), 8 threads per pixel
    {
        int p = t >> 3, lg = t & 7;
        float mx = -1e30f;
        for (int c = lg; c < CMn; c += 8) mx = fmaxf(mx, ls[p][c]);
        for (int o = 4; o > 0; o >>= 1) mx = fmaxf(mx, __shfl_xor_sync(0xffffffffu, mx, o, 8));
        float s = 0.f;
        for (int c = lg; c < CMn; c += 8) { float e = expf(ls[p][c] - mx); ls[p][c] = e; s += e; }
        for (int o = 4; o > 0; o >>= 1) s += __shfl_xor_sync(0xffffffffu, s, o, 8);
        float inv = 1.0f / s;
        for (int c = lg; c < CMn; c += 8) ls[p][c] *= inv;
    }
    __syncthreads();

    // out[p][m=t] = sum_c att[p][c] * v[c][t]
    float acc[32];
#pragma unroll
    for (int p = 0; p < 32; p++) acc[p] = 0.f;
    for (int c = 0; c < CMn; c++) {
        float vv = g_vv[c * MID + t];
#pragma unroll
        for (int p = 0; p < 32; p++) acc[p] += ls[p][c] * vv;
    }
    float* ob = g_o + ((size_t)b * HW + row * Ww + j0) * MID;
#pragma unroll
    for (int p = 0; p < 32; p++) ob[(size_t)p * MID + t] = acc[p];
}

// ---------------- 8. y = O @ Wc, BN(eval), ReLU, channel-major store ----------
// O: [65536 x 256] row-major; Wc: [256 x 512]; grid (8, 1024), block (16,16)
__global__ void k_conv(const float* __restrict__ Wc,
                       const float* __restrict__ gamma, const float* __restrict__ beta,
                       const float* __restrict__ mean, const float* __restrict__ var,
                       float* __restrict__ y) {
    int mBase = blockIdx.y * 64;   // row (b*HW + pix)
    int nBase = blockIdx.x * 64;   // out channel
    __shared__ float As[64][17];
    __shared__ float Bs[16][65];
    int tx = threadIdx.x, ty = threadIdx.y, tid = ty * 16 + tx;
    float acc[4][4] = {};
    for (int k0 = 0; k0 < 256; k0 += 16) {
#pragma unroll
        for (int e = tid; e < 1024; e += 256) {
            int r = e >> 4, kk = e & 15;
            As[r][kk] = g_o[(size_t)(mBase + r) * MID + k0 + kk];
        }
#pragma unroll
        for (int e = tid; e < 1024; e += 256) {
            int kk = e >> 6, nn = e & 63;
            Bs[kk][nn] = Wc[(k0 + kk) * Cc + nBase + nn];
        }
        __syncthreads();
#pragma unroll
        for (int kk = 0; kk < 16; kk++) {
            float a[4], bb[4];
#pragma unroll
            for (int i = 0; i < 4; i++) a[i] = As[tx + i * 16][kk];
#pragma unroll
            for (int j = 0; j < 4; j++) bb[j] = Bs[kk][ty + j * 16];
#pragma unroll
            for (int i = 0; i < 4; i++)
#pragma unroll
                for (int j = 0; j < 4; j++) acc[i][j] += a[i] * bb[j];
        }
        __syncthreads();
    }
#pragma unroll
    for (int j = 0; j < 4; j++) {
        int ch = nBase + ty + j * 16;
        float iv = gamma[ch] / sqrtf(var[ch] + 1e-5f);
        float ad = beta[ch] - mean[ch] * iv;
#pragma unroll
        for (int i = 0; i < 4; i++) {
            int r = mBase + tx + i * 16;
            int bb = r >> 14;          // b (HW = 2^14)
            int pix = r & 16383;
            float v = acc[i][j] * iv + ad;
            y[((size_t)bb * Cc + ch) * HW + pix] = fmaxf(v, 0.f);
        }
    }
}

// ---------------- launcher ----------------
extern "C" void kernel_launch(void* const* d_in, const int* in_sizes, int n_in,
                              void* d_out, int out_size) {
    const float* x   = (const float*)d_in[0];
    const float* sim = (const float*)d_in[1];
    const float* gcc = (const float*)d_in[2];
    const float* Wq  = (const float*)d_in[3];
    const float* bq  = (const float*)d_in[4];
    const float* Wk  = (const float*)d_in[5];
    const float* bk  = (const float*)d_in[6];
    const float* Wv  = (const float*)d_in[7];
    const float* bv  = (const float*)d_in[8];
    const float* Wc  = (const float*)d_in[9];
    const float* gm  = (const float*)d_in[10];
    const float* bt  = (const float*)d_in[11];
    const float* mn  = (const float*)d_in[12];
    const float* vr  = (const float*)d_in[13];
    float* y = (float*)d_out;
    float* tail = y + (size_t)Bsz * Cc * HW;

    k_pool<<<Bsz * CMn * Np, 256>>>(sim, tail);
    k_softmax<<<Bsz * Np * CMn, 256>>>(sim);
    k_local<<<dim3(8, 3, 64), dim3(16, 16)>>>(x);
    k_kproj<<<dim3(4, 3, 64), dim3(16, 16)>>>(Wk, bk);
    k_v<<<CMn, 256>>>(gcc, Wv, bv);
    k_q<<<dim3(4, 256, 4), dim3(16, 16)>>>(x, Wq, bq);
    k_att<<<2048, 256>>>();
    k_conv<<<dim3(8, 1024), dim3(16, 16)>>>(Wc, gm, bt, mn, vr, y);
}

// round 3
// speedup vs baseline: 1.7071x; 1.7071x over previous
#include <cuda_runtime.h>
#include <cuda_fp16.h>
#include <mma.h>
#include <math.h>

using namespace nvcuda;

#define Bsz 4
#define Cc 512
#define MID 256
#define CMn 76
#define Hh 128
#define Ww 128
#define HW 16384
#define Pp 1024
#define Np 16

// ---------------- static scratch ----------------
__device__ float g_pool[Bsz * CMn * Np];
__device__ float g_smx[(size_t)Bsz * Np * CMn * Pp];
__device__ float g_local[(size_t)Bsz * Np * CMn * Cc];
__device__ float g_kk[(size_t)Bsz * Np * CMn * MID];
__device__ float g_vv[CMn * MID];
__device__ float g_q[(size_t)Bsz * HW * MID];          // fp32 q
__device__ __half g_oh[(size_t)Bsz * HW * MID];        // attention out (half)
__device__ __half g_Wq_h[Cc * MID];
__device__ __half g_Wc_h[MID * Cc];
__device__ float g_qbias[16 * MID];                    // bq replicated 16 rows

// ---------------- 0. setup: convert weights to half, build bias tile -------
__global__ void k_setup(const float* __restrict__ Wq, const float* __restrict__ Wc,
                        const float* __restrict__ bq) {
    int t = blockIdx.x * blockDim.x + threadIdx.x;
    int stride = gridDim.x * blockDim.x;
    for (int i = t; i < Cc * MID; i += stride) {
        g_Wq_h[i] = __float2half(Wq[i]);
        g_Wc_h[i] = __float2half(Wc[i]);
    }
    for (int i = t; i < 16 * MID; i += stride) g_qbias[i] = bq[i & (MID - 1)];
}

// ---------------- 1. adaptive avg pool ----------------
__global__ void k_pool(const float* __restrict__ sim, float* __restrict__ out_tail) {
    int id = blockIdx.x;
    int n  = id & 15;
    int bc = id >> 4;
    int i0 = (n >> 2) * 32, j0 = (n & 3) * 32;
    const float* base = sim + (size_t)bc * HW;
    float s = 0.f;
    for (int p = threadIdx.x; p < 1024; p += 256) {
        int pi = p >> 5, pj = p & 31;
        s += base[(i0 + pi) * Ww + j0 + pj];
    }
    __shared__ float red[256];
    red[threadIdx.x] = s; __syncthreads();
    for (int o = 128; o > 0; o >>= 1) {
        if (threadIdx.x < o) red[threadIdx.x] += red[threadIdx.x + o];
        __syncthreads();
    }
    if (threadIdx.x == 0) {
        float m = red[0] * (1.0f / 1024.0f);
        g_pool[id]   = m;
        out_tail[id] = m;
    }
}

// ---------------- 2. softmax over pixels within patch ----------------
__global__ void k_softmax(const float* __restrict__ sim) {
    int id = blockIdx.x;
    int cm = id % CMn;
    int bn = id / CMn;
    int n = bn & 15, b = bn >> 4;
    int i0 = (n >> 2) * 32, j0 = (n & 3) * 32;
    const float* base = sim + ((size_t)b * CMn + cm) * HW;
    int t = threadIdx.x;
    float v[4];
    float mx = -1e30f;
#pragma unroll
    for (int it = 0; it < 4; it++) {
        int p = t + it * 256;
        int pi = p >> 5, pj = p & 31;
        v[it] = base[(i0 + pi) * Ww + j0 + pj];
        mx = fmaxf(mx, v[it]);
    }
    __shared__ float red[256];
    red[t] = mx; __syncthreads();
    for (int o = 128; o > 0; o >>= 1) {
        if (t < o) red[t] = fmaxf(red[t], red[t + o]);
        __syncthreads();
    }
    float gmx = red[0]; __syncthreads();
    float s = 0.f;
#pragma unroll
    for (int it = 0; it < 4; it++) { v[it] = expf(v[it] - gmx); s += v[it]; }
    red[t] = s; __syncthreads();
    for (int o = 128; o > 0; o >>= 1) {
        if (t < o) red[t] += red[t + o];
        __syncthreads();
    }
    float inv = 1.0f / red[0];
    float* dst = g_smx + ((size_t)bn * CMn + cm) * Pp;
#pragma unroll
    for (int it = 0; it < 4; it++) { int p = t + it * 256; dst[p] = v[it] * inv; }
}

// ---------------- 3. local = smx^T @ xs * conf (fp32 SIMT) ----------------
__global__ void k_local(const float* __restrict__ x) {
    int bn = blockIdx.z;
    int b = bn >> 4, n = bn & 15;
    int i0 = (n >> 2) * 32, j0 = (n & 3) * 32;
    int mBase = blockIdx.y * 32;
    int nBase = blockIdx.x * 64;
    __shared__ float As[32][17];
    __shared__ float Bs[64][17];
    const float* Arow = g_smx + (size_t)bn * CMn * Pp;
    const float* xb = x + (size_t)b * Cc * HW;
    int tx = threadIdx.x, ty = threadIdx.y, tid = ty * 16 + tx;
    float acc[2][4] = {};
    for (int p0 = 0; p0 < 1024; p0 += 16) {
        int pi = p0 >> 5;
        int pjB = p0 & 31;
#pragma unroll
        for (int e = tid; e < 512; e += 256) {
            int r = e >> 4, pp = e & 15;
            int c = mBase + r;
            As[r][pp] = (c < CMn) ? Arow[(size_t)c * Pp + p0 + pp] : 0.f;
        }
#pragma unroll
        for (int e = tid; e < 1024; e += 256) {
            int r = e >> 4, pp = e & 15;
            int k = nBase + r;
            Bs[r][pp] = xb[(size_t)k * HW + (i0 + pi) * Ww + j0 + pjB + pp];
        }
        __syncthreads();
#pragma unroll
        for (int pp = 0; pp < 16; pp++) {
            float a0 = As[ty][pp], a1 = As[ty + 16][pp];
            float b0 = Bs[tx][pp], b1 = Bs[tx + 16][pp];
            float b2 = Bs[tx + 32][pp], b3 = Bs[tx + 48][pp];
            acc[0][0] += a0 * b0; acc[0][1] += a0 * b1; acc[0][2] += a0 * b2; acc[0][3] += a0 * b3;
            acc[1][0] += a1 * b0; acc[1][1] += a1 * b1; acc[1][2] += a1 * b2; acc[1][3] += a1 * b3;
        }
        __syncthreads();
    }
#pragma unroll
    for (int i = 0; i < 2; i++) {
        int c = mBase + ty + i * 16;
        if (c < CMn) {
            float conf = g_pool[(b * CMn + c) * 16 + n];
            float* dst = g_local + ((size_t)bn * CMn + c) * Cc;
#pragma unroll
            for (int j = 0; j < 4; j++) {
                int k = nBase + tx + j * 16;
                dst[k] = acc[i][j] * conf;
            }
        }
    }
}

// ---------------- 4. k = local @ Wk + bk (fp32 SIMT) ----------------
__global__ void k_kproj(const float* __restrict__ Wk, const float* __restrict__ bk) {
    int bn = blockIdx.z;
    int mBase = blockIdx.y * 32;
    int nBase = blockIdx.x * 64;
    __shared__ float As[32][17];
    __shared__ float Bs[16][65];
    const float* Ap = g_local + (size_t)bn * CMn * Cc;
    int tx = threadIdx.x, ty = threadIdx.y, tid = ty * 16 + tx;
    float acc[2][4] = {};
    for (int k0 = 0; k0 < 512; k0 += 16) {
#pragma unroll
        for (int e = tid; e < 512; e += 256) {
            int r = e >> 4, kk = e & 15;
            int c = mBase + r;
            As[r][kk] = (c < CMn) ? Ap[(size_t)c * Cc + k0 + kk] : 0.f;
        }
#pragma unroll
        for (int e = tid; e < 1024; e += 256) {
            int kk = e >> 6, nn = e & 63;
            Bs[kk][nn] = Wk[(k0 + kk) * MID + nBase + nn];
        }
        __syncthreads();
#pragma unroll
        for (int kk = 0; kk < 16; kk++) {
            float a0 = As[ty][kk], a1 = As[ty + 16][kk];
#pragma unroll
            for (int j = 0; j < 4; j++) {
                float bb = Bs[kk][tx + j * 16];
                acc[0][j] += a0 * bb;
                acc[1][j] += a1 * bb;
            }
        }
        __syncthreads();
    }
#pragma unroll
    for (int i = 0; i < 2; i++) {
        int c = mBase + ty + i * 16;
        if (c < CMn) {
            float* dst = g_kk + ((size_t)bn * CMn + c) * MID;
#pragma unroll
            for (int j = 0; j < 4; j++) {
                int nn = nBase + tx + j * 16;
                dst[nn] = acc[i][j] + bk[nn];
            }
        }
    }
}

// ---------------- 5. v = g @ Wv + bv ----------------
__global__ void k_v(const float* __restrict__ g, const float* __restrict__ Wv,
                    const float* __restrict__ bv) {
    __shared__ float sg[512];
    int c = blockIdx.x, t = threadIdx.x;
    for (int k = t; k < 512; k += 256) sg[k] = g[c * 512 + k];
    __syncthreads();
    float acc = 0.f;
    for (int k = 0; k < 512; k++) acc += sg[k] * Wv[k * MID + t];
    g_vv[c * MID + t] = acc + bv[t];
}

// ---------------- 6. q = x^T @ Wq + bq  (WMMA fp16) ----------------
// per b: [16384 x 512] x [512 x 256]; block tile 128x128, BK=32
// grid (2, 128, 4), block 256 (8 warps: 4 M x 2 N, warp tile 32x64)
__global__ __launch_bounds__(256, 1) void k_q_w(const float* __restrict__ x) {
    __shared__ __align__(16) __half As[32][136];   // [k][m] (A col-major)
    __shared__ __align__(16) __half Bs[32][136];   // [k][n] (B row-major)
    int b = blockIdx.z;
    int mBase = blockIdx.y * 128;
    int nBase = blockIdx.x * 128;
    const float* xb = x + (size_t)b * Cc * HW;
    int tid = threadIdx.x;
    int wid = tid >> 5;
    int wm = wid & 3;          // 4 warps along M
    int wn = wid >> 2;         // 2 warps along N

    wmma::fragment<wmma::accumulator, 16, 16, 16, float> c[2][4];
#pragma unroll
    for (int i = 0; i < 2; i++)
#pragma unroll
        for (int j = 0; j < 4; j++)
            wmma::load_matrix_sync(c[i][j], g_qbias + nBase + wn * 64 + j * 16, MID,
                                   wmma::mem_row_major);

    for (int k0 = 0; k0 < 512; k0 += 32) {
        // A: 32x128 floats -> half (col-major staging: m contiguous)
#pragma unroll
        for (int l = 0; l < 4; l++) {
            int idx = tid + l * 256;            // 1024 float4
            int kk = idx >> 5;
            int m = (idx & 31) * 4;
            float4 v = *(const float4*)&xb[(size_t)(k0 + kk) * HW + mBase + m];
            As[kk][m]     = __float2half(v.x);
            As[kk][m + 1] = __float2half(v.y);
            As[kk][m + 2] = __float2half(v.z);
            As[kk][m + 3] = __float2half(v.w);
        }
        // B: 32x128 halves
#pragma unroll
        for (int l = 0; l < 2; l++) {
            int idx = tid + l * 256;            // 512 uint4 (8 halves)
            int kk = idx >> 4;
            int n = (idx & 15) * 8;
            *(uint4*)&Bs[kk][n] = *(const uint4*)&g_Wq_h[(k0 + kk) * MID + nBase + n];
        }
        __syncthreads();
#pragma unroll
        for (int ks = 0; ks < 32; ks += 16) {
            wmma::fragment<wmma::matrix_a, 16, 16, 16, __half, wmma::col_major> af[2];
            wmma::fragment<wmma::matrix_b, 16, 16, 16, __half, wmma::row_major> bf[4];
#pragma unroll
            for (int i = 0; i < 2; i++)
                wmma::load_matrix_sync(af[i], &As[ks][wm * 32 + i * 16], 136);
#pragma unroll
            for (int j = 0; j < 4; j++)
                wmma::load_matrix_sync(bf[j], &Bs[ks][wn * 64 + j * 16], 136);
#pragma unroll
            for (int i = 0; i < 2; i++)
#pragma unroll
                for (int j = 0; j < 4; j++)
                    wmma::mma_sync(c[i][j], af[i], bf[j], c[i][j]);
        }
        __syncthreads();
    }
#pragma unroll
    for (int i = 0; i < 2; i++) {
        int row = b * HW + mBase + wm * 32 + i * 16;
#pragma unroll
        for (int j = 0; j < 4; j++) {
            int col = nBase + wn * 64 + j * 16;
            wmma::store_matrix_sync(g_q + (size_t)row * MID + col, c[i][j], MID,
                                    wmma::mem_row_major);
        }
    }
}

// ---------------- 7. fused attention (fp32) -> writes half O ----------------
__global__ void k_att() {
    __shared__ float qs[256][33];
    __shared__ float ls[32][81];
    int id = blockIdx.x;
    int pi = id & 31;
    int bn = id >> 5;
    int b = bn >> 4, n = bn & 15;
    int i0 = (n >> 2) * 32, j0 = (n & 3) * 32;
    int row = i0 + pi;
    int t = threadIdx.x;

    const float* qbase = g_q + ((size_t)b * HW + row * Ww + j0) * MID;
#pragma unroll
    for (int e = t; e < 8192; e += 256) {
        int p = e >> 8, m = e & 255;
        qs[m][p] = qbase[(size_t)p * MID + m];
    }
    __syncthreads();

    const float* kbase = g_kk + (size_t)bn * CMn * MID;
    for (int idx = t; idx < 32 * CMn; idx += 256) {
        int p = idx & 31, c = idx >> 5;
        const float4* k4 = (const float4*)(kbase + c * MID);
        float s = 0.f;
#pragma unroll 8
        for (int m4 = 0; m4 < 64; m4++) {
            float4 kv = k4[m4];
            s += qs[m4 * 4 + 0][p] * kv.x + qs[m4 * 4 + 1][p] * kv.y
               + qs[m4 * 4 + 2][p] * kv.z + qs[m4 * 4 + 3][p] * kv.w;
        }
        ls[p][c] = s;
    }
    __syncthreads();

    {
        int p = t >> 3, lg = t & 7;
        float mx = -1e30f;
        for (int c = lg; c < CMn; c += 8) mx = fmaxf(mx, ls[p][c]);
        for (int o = 4; o > 0; o >>= 1) mx = fmaxf(mx, __shfl_xor_sync(0xffffffffu, mx, o, 8));
        float s = 0.f;
        for (int c = lg; c < CMn; c += 8) { float e = expf(ls[p][c] - mx); ls[p][c] = e; s += e; }
        for (int o = 4; o > 0; o >>= 1) s += __shfl_xor_sync(0xffffffffu, s, o, 8);
        float inv = 1.0f / s;
        for (int c = lg; c < CMn; c += 8) ls[p][c] *= inv;
    }
    __syncthreads();

    float acc[32];
#pragma unroll
    for (int p = 0; p < 32; p++) acc[p] = 0.f;
    for (int c = 0; c < CMn; c++) {
        float vv = g_vv[c * MID + t];
#pragma unroll
        for (int p = 0; p < 32; p++) acc[p] += ls[p][c] * vv;
    }
    __half* ob = g_oh + ((size_t)b * HW + row * Ww + j0) * MID;
#pragma unroll
    for (int p = 0; p < 32; p++) ob[(size_t)p * MID + t] = __float2half(acc[p]);
}

// ---------------- 8. conv (WMMA fp16) + BN + ReLU, channel-major ----------
// C[65536x512] = O_h[65536x256] @ Wc_h[256x512]; block 128x64, BK=32
// grid (8, 512), block 256 (8 warps: 4 M x 2 N, warp tile 32x32)
__global__ __launch_bounds__(256, 1) void k_conv_w(const float* __restrict__ gamma,
                                                   const float* __restrict__ beta,
                                                   const float* __restrict__ mean,
                                                   const float* __restrict__ var,
                                                   float* __restrict__ y) {
    __shared__ __align__(16) union {
        struct { __half A[128][40]; __half B[32][72]; } ab;
        float C[64 * 136];                 // [n][m], ld 136
    } u;
    int nBase = blockIdx.x * 64;
    int mBase = blockIdx.y * 128;
    int tid = threadIdx.x;
    int wid = tid >> 5;
    int wm = wid & 3;
    int wn = wid >> 2;

    wmma::fragment<wmma::accumulator, 16, 16, 16, float> c[2][2];
#pragma unroll
    for (int i = 0; i < 2; i++)
#pragma unroll
        for (int j = 0; j < 2; j++) wmma::fill_fragment(c[i][j], 0.f);

    for (int k0 = 0; k0 < 256; k0 += 32) {
#pragma unroll
        for (int l = 0; l < 2; l++) {
            int idx = tid + l * 256;           // 512 uint4
            int m = idx >> 2;
            int kk = (idx & 3) * 8;
            *(uint4*)&u.ab.A[m][kk] = *(const uint4*)&g_oh[(size_t)(mBase + m) * MID + k0 + kk];
        }
        {
            int kk = tid >> 3;                 // 256 uint4
            int n = (tid & 7) * 8;
            *(uint4*)&u.ab.B[kk][n] = *(const uint4*)&g_Wc_h[(k0 + kk) * Cc + nBase + n];
        }
        __syncthreads();
#pragma unroll
        for (int ks = 0; ks < 32; ks += 16) {
            wmma::fragment<wmma::matrix_a, 16, 16, 16, __half, wmma::row_major> af[2];
            wmma::fragment<wmma::matrix_b, 16, 16, 16, __half, wmma::row_major> bf[2];
#pragma unroll
            for (int i = 0; i < 2; i++)
                wmma::load_matrix_sync(af[i], &u.ab.A[wm * 32 + i * 16][ks], 40);
#pragma unroll
            for (int j = 0; j < 2; j++)
                wmma::load_matrix_sync(bf[j], &u.ab.B[ks][wn * 32 + j * 16], 72);
#pragma unroll
            for (int i = 0; i < 2; i++)
#pragma unroll
                for (int j = 0; j < 2; j++)
                    wmma::mma_sync(c[i][j], af[i], bf[j], c[i][j]);
        }
        __syncthreads();
    }

    // stage C col-major: element (m_local, n_local) at C[n*136 + m]
#pragma unroll
    for (int i = 0; i < 2; i++)
#pragma unroll
        for (int j = 0; j < 2; j++)
            wmma::store_matrix_sync(&u.C[(wn * 32 + j * 16) * 136 + wm * 32 + i * 16],
                                    c[i][j], 136, wmma::mem_col_major);
    __syncthreads();

    // BN + ReLU + channel-major scatter
    {
        int n = tid >> 2;               // 0..63
        int q4 = tid & 3;
        int ch = nBase + n;
        float iv = gamma[ch] / sqrtf(var[ch] + 1e-5f);
        float ad = beta[ch] - mean[ch] * iv;
        int bb = mBase >> 14;
        int pixBase = mBase & 16383;
        float* yrow = y + ((size_t)bb * Cc + ch) * HW + pixBase;
        const float* crow = &u.C[n * 136];
#pragma unroll
        for (int l = 0; l < 8; l++) {
            int m = (q4 + l * 4) * 4;
            float4 v = *(const float4*)&crow[m];
            v.x = fmaxf(v.x * iv + ad, 0.f);
            v.y = fmaxf(v.y * iv + ad, 0.f);
            v.z = fmaxf(v.z * iv + ad, 0.f);
            v.w = fmaxf(v.w * iv + ad, 0.f);
            *(float4*)&yrow[m] = v;
        }
    }
}

// ---------------- launcher ----------------
extern "C" void kernel_launch(void* const* d_in, const int* in_sizes, int n_in,
                              void* d_out, int out_size) {
    const float* x   = (const float*)d_in[0];
    const float* sim = (const float*)d_in[1];
    const float* gcc = (const float*)d_in[2];
    const float* Wq  = (const float*)d_in[3];
    const float* bq  = (const float*)d_in[4];
    const float* Wk  = (const float*)d_in[5];
    const float* bk  = (const float*)d_in[6];
    const float* Wv  = (const float*)d_in[7];
    const float* bv  = (const float*)d_in[8];
    const float* Wc  = (const float*)d_in[9];
    const float* gm  = (const float*)d_in[10];
    const float* bt  = (const float*)d_in[11];
    const float* mn  = (const float*)d_in[12];
    const float* vr  = (const float*)d_in[13];
    float* y = (float*)d_out;
    float* tail = y + (size_t)Bsz * Cc * HW;

    k_setup<<<128, 256>>>(Wq, Wc, bq);
    k_pool<<<Bsz * CMn * Np, 256>>>(sim, tail);
    k_softmax<<<Bsz * Np * CMn, 256>>>(sim);
    k_local<<<dim3(8, 3, 64), dim3(16, 16)>>>(x);
    k_kproj<<<dim3(4, 3, 64), dim3(16, 16)>>>(Wk, bk);
    k_v<<<CMn, 256>>>(gcc, Wv, bv);
    k_q_w<<<dim3(2, 128, 4), 256>>>(x);
    k_att<<<2048, 256>>>();
    k_conv_w<<<dim3(8, 512), 256>>>(gm, bt, mn, vr, y);
}

// round 4
// speedup vs baseline: 2.3019x; 1.3484x over previous
#include <cuda_runtime.h>
#include <cuda_fp16.h>
#include <mma.h>
#include <math.h>

using namespace nvcuda;

#define Bsz 4
#define Cc 512
#define MID 256
#define CMn 76
#define Hh 128
#define Ww 128
#define HW 16384
#define Pp 1024
#define Np 16

// ---------------- static scratch ----------------
__device__ float g_pool[Bsz * CMn * Np];
__device__ float g_smx[(size_t)Bsz * Np * CMn * Pp];
__device__ __half g_localh[(size_t)Bsz * Np * CMn * Cc];   // half local (conf folded)
__device__ float g_kk[(size_t)Bsz * Np * CMn * MID];
__device__ float g_vv[CMn * MID];
__device__ float g_q[(size_t)Bsz * HW * MID];          // fp32 q
__device__ __half g_oh[(size_t)Bsz * HW * MID];        // attention out (half)
__device__ __half g_Wq_h[Cc * MID];
__device__ __half g_Wk_h[Cc * MID];
__device__ __half g_Wc_h[MID * Cc];
__device__ float g_qbias[16 * MID];                    // bq replicated 16 rows

// ---------------- 0. setup ----------------
__global__ void k_setup(const float* __restrict__ Wq, const float* __restrict__ Wk,
                        const float* __restrict__ Wc, const float* __restrict__ bq) {
    int t = blockIdx.x * blockDim.x + threadIdx.x;
    int stride = gridDim.x * blockDim.x;
    for (int i = t; i < Cc * MID; i += stride) {
        g_Wq_h[i] = __float2half(Wq[i]);
        g_Wk_h[i] = __float2half(Wk[i]);
        g_Wc_h[i] = __float2half(Wc[i]);
    }
    for (int i = t; i < 16 * MID; i += stride) g_qbias[i] = bq[i & (MID - 1)];
}

// ---------------- 1. adaptive avg pool ----------------
__global__ void k_pool(const float* __restrict__ sim, float* __restrict__ out_tail) {
    int id = blockIdx.x;
    int n  = id & 15;
    int bc = id >> 4;
    int i0 = (n >> 2) * 32, j0 = (n & 3) * 32;
    const float* base = sim + (size_t)bc * HW;
    float s = 0.f;
    for (int p = threadIdx.x; p < 1024; p += 256) {
        int pi = p >> 5, pj = p & 31;
        s += base[(i0 + pi) * Ww + j0 + pj];
    }
    __shared__ float red[256];
    red[threadIdx.x] = s; __syncthreads();
    for (int o = 128; o > 0; o >>= 1) {
        if (threadIdx.x < o) red[threadIdx.x] += red[threadIdx.x + o];
        __syncthreads();
    }
    if (threadIdx.x == 0) {
        float m = red[0] * (1.0f / 1024.0f);
        g_pool[id]   = m;
        out_tail[id] = m;
    }
}

// ---------------- 2. softmax over pixels within patch ----------------
__global__ void k_softmax(const float* __restrict__ sim) {
    int id = blockIdx.x;
    int cm = id % CMn;
    int bn = id / CMn;
    int n = bn & 15, b = bn >> 4;
    int i0 = (n >> 2) * 32, j0 = (n & 3) * 32;
    const float* base = sim + ((size_t)b * CMn + cm) * HW;
    int t = threadIdx.x;
    float v[4];
    float mx = -1e30f;
#pragma unroll
    for (int it = 0; it < 4; it++) {
        int p = t + it * 256;
        int pi = p >> 5, pj = p & 31;
        v[it] = base[(i0 + pi) * Ww + j0 + pj];
        mx = fmaxf(mx, v[it]);
    }
    __shared__ float red[256];
    red[t] = mx; __syncthreads();
    for (int o = 128; o > 0; o >>= 1) {
        if (t < o) red[t] = fmaxf(red[t], red[t + o]);
        __syncthreads();
    }
    float gmx = red[0]; __syncthreads();
    float s = 0.f;
#pragma unroll
    for (int it = 0; it < 4; it++) { v[it] = expf(v[it] - gmx); s += v[it]; }
    red[t] = s; __syncthreads();
    for (int o = 128; o > 0; o >>= 1) {
        if (t < o) red[t] += red[t + o];
        __syncthreads();
    }
    float inv = 1.0f / red[0];
    float* dst = g_smx + ((size_t)bn * CMn + cm) * Pp;
#pragma unroll
    for (int it = 0; it < 4; it++) { int p = t + it * 256; dst[p] = v[it] * inv; }
}

// ---------------- 3. local = smx^T @ xs * conf  (WMMA fp16) ----------------
// per (b,n): [80(76) x 1024] @ [1024 x 512]; N tile 128 -> grid (4, 64)
// block 320 threads = 10 warps (5 M x 2 N), warp tile 16x64, BK=32
__global__ __launch_bounds__(320, 1) void k_local_w(const float* __restrict__ x) {
    __shared__ __align__(16) union {
        struct { __half A[80][40]; __half B[128][40]; } ab;   // [c][p], [n][p]
        float C[80 * 136];
    } u;
    int bn = blockIdx.y;
    int b = bn >> 4, n_p = bn & 15;
    int i0 = (n_p >> 2) * 32, j0 = (n_p & 3) * 32;
    int nBase = blockIdx.x * 128;
    const float* Arow = g_smx + (size_t)bn * CMn * Pp;
    const float* xb = x + (size_t)b * Cc * HW;
    int tid = threadIdx.x;
    int wid = tid >> 5;
    int wm = wid % 5;
    int wn = wid / 5;

    wmma::fragment<wmma::accumulator, 16, 16, 16, float> c[4];
#pragma unroll
    for (int j = 0; j < 4; j++) wmma::fill_fragment(c[j], 0.f);

    for (int p0 = 0; p0 < 1024; p0 += 32) {
        int pi = p0 >> 5;
        // A: 80 rows x 32 p (640 float4)
#pragma unroll
        for (int l = 0; l < 2; l++) {
            int idx = tid + l * 320;
            int cc = idx >> 3;
            int pp = (idx & 7) * 4;
            if (cc < 76) {
                float4 v = *(const float4*)&Arow[(size_t)cc * Pp + p0 + pp];
                u.ab.A[cc][pp]     = __float2half(v.x);
                u.ab.A[cc][pp + 1] = __float2half(v.y);
                u.ab.A[cc][pp + 2] = __float2half(v.z);
                u.ab.A[cc][pp + 3] = __float2half(v.w);
            } else {
                *(__half2*)&u.ab.A[cc][pp] = __half2(__float2half(0.f), __float2half(0.f));
                *(__half2*)&u.ab.A[cc][pp + 2] = __half2(__float2half(0.f), __float2half(0.f));
            }
        }
        // B: 128 channels x 32 p (1024 float4)
        for (int idx = tid; idx < 1024; idx += 320) {
            int nn = idx >> 3;
            int pp = (idx & 7) * 4;
            float4 v = *(const float4*)&xb[(size_t)(nBase + nn) * HW + (i0 + pi) * Ww + j0 + pp];
            u.ab.B[nn][pp]     = __float2half(v.x);
            u.ab.B[nn][pp + 1] = __float2half(v.y);
            u.ab.B[nn][pp + 2] = __float2half(v.z);
            u.ab.B[nn][pp + 3] = __float2half(v.w);
        }
        __syncthreads();
#pragma unroll
        for (int ks = 0; ks < 32; ks += 16) {
            wmma::fragment<wmma::matrix_a, 16, 16, 16, __half, wmma::row_major> af;
            wmma::fragment<wmma::matrix_b, 16, 16, 16, __half, wmma::col_major> bf[4];
            wmma::load_matrix_sync(af, &u.ab.A[wm * 16][ks], 40);
#pragma unroll
            for (int j = 0; j < 4; j++)
                wmma::load_matrix_sync(bf[j], &u.ab.B[wn * 64 + j * 16][ks], 40);
#pragma unroll
            for (int j = 0; j < 4; j++) wmma::mma_sync(c[j], af, bf[j], c[j]);
        }
        __syncthreads();
    }
#pragma unroll
    for (int j = 0; j < 4; j++)
        wmma::store_matrix_sync(&u.C[(wm * 16) * 136 + wn * 64 + j * 16], c[j], 136,
                                wmma::mem_row_major);
    __syncthreads();
    // epilogue: * conf, write half
    for (int idx = tid; idx < 76 * 128; idx += 320) {
        int cc = idx >> 7, nn = idx & 127;
        float conf = g_pool[(b * CMn + cc) * 16 + n_p];
        g_localh[((size_t)bn * CMn + cc) * Cc + nBase + nn] =
            __float2half(u.C[cc * 136 + nn] * conf);
    }
}

// ---------------- 4. k = local @ Wk + bk (WMMA fp16) ----------------
// per bn: [80(76) x 512] @ [512 x 256]; N tile 128 -> grid (2, 64)
// block 320 = 10 warps (5 M x 2 N), BK=32
__global__ __launch_bounds__(320, 1) void k_kproj_w(const float* __restrict__ bk) {
    __shared__ __align__(16) union {
        struct { __half A[80][40]; __half B[32][136]; } ab;
        float C[80 * 136];
    } u;
    int bn = blockIdx.y;
    int nBase = blockIdx.x * 128;
    const __half* Ap = g_localh + (size_t)bn * CMn * Cc;
    int tid = threadIdx.x;
    int wid = tid >> 5;
    int wm = wid % 5;
    int wn = wid / 5;

    wmma::fragment<wmma::accumulator, 16, 16, 16, float> c[4];
#pragma unroll
    for (int j = 0; j < 4; j++) wmma::fill_fragment(c[j], 0.f);

    for (int k0 = 0; k0 < 512; k0 += 32) {
        // A: 80 x 32 halves (320 uint4) - one per thread
        {
            int cc = tid >> 2;
            int h8 = (tid & 3) * 8;
            if (cc < 76)
                *(uint4*)&u.ab.A[cc][h8] = *(const uint4*)&Ap[(size_t)cc * Cc + k0 + h8];
            else {
                uint4 z = {0, 0, 0, 0};
                *(uint4*)&u.ab.A[cc][h8] = z;
            }
        }
        // B: 32 x 128 halves (512 uint4)
        for (int idx = tid; idx < 512; idx += 320) {
            int kk = idx >> 4;
            int nn = (idx & 15) * 8;
            *(uint4*)&u.ab.B[kk][nn] = *(const uint4*)&g_Wk_h[(k0 + kk) * MID + nBase + nn];
        }
        __syncthreads();
#pragma unroll
        for (int ks = 0; ks < 32; ks += 16) {
            wmma::fragment<wmma::matrix_a, 16, 16, 16, __half, wmma::row_major> af;
            wmma::fragment<wmma::matrix_b, 16, 16, 16, __half, wmma::row_major> bf[4];
            wmma::load_matrix_sync(af, &u.ab.A[wm * 16][ks], 40);
#pragma unroll
            for (int j = 0; j < 4; j++)
                wmma::load_matrix_sync(bf[j], &u.ab.B[ks][wn * 64 + j * 16], 136);
#pragma unroll
            for (int j = 0; j < 4; j++) wmma::mma_sync(c[j], af, bf[j], c[j]);
        }
        __syncthreads();
    }
#pragma unroll
    for (int j = 0; j < 4; j++)
        wmma::store_matrix_sync(&u.C[(wm * 16) * 136 + wn * 64 + j * 16], c[j], 136,
                                wmma::mem_row_major);
    __syncthreads();
    for (int idx = tid; idx < 76 * 128; idx += 320) {
        int cc = idx >> 7, nn = idx & 127;
        g_kk[((size_t)bn * CMn + cc) * MID + nBase + nn] =
            u.C[cc * 136 + nn] + bk[nBase + nn];
    }
}

// ---------------- 5. v = g @ Wv + bv ----------------
__global__ void k_v(const float* __restrict__ g, const float* __restrict__ Wv,
                    const float* __restrict__ bv) {
    __shared__ float sg[512];
    int c = blockIdx.x, t = threadIdx.x;
    for (int k = t; k < 512; k += 256) sg[k] = g[c * 512 + k];
    __syncthreads();
    float acc = 0.f;
    for (int k = 0; k < 512; k++) acc += sg[k] * Wv[k * MID + t];
    g_vv[c * MID + t] = acc + bv[t];
}

// ---------------- 6. q = x^T @ Wq + bq  (WMMA fp16) ----------------
__global__ __launch_bounds__(256, 1) void k_q_w(const float* __restrict__ x) {
    __shared__ __align__(16) __half As[32][136];
    __shared__ __align__(16) __half Bs[32][136];
    int b = blockIdx.z;
    int mBase = blockIdx.y * 128;
    int nBase = blockIdx.x * 128;
    const float* xb = x + (size_t)b * Cc * HW;
    int tid = threadIdx.x;
    int wid = tid >> 5;
    int wm = wid & 3;
    int wn = wid >> 2;

    wmma::fragment<wmma::accumulator, 16, 16, 16, float> c[2][4];
#pragma unroll
    for (int i = 0; i < 2; i++)
#pragma unroll
        for (int j = 0; j < 4; j++)
            wmma::load_matrix_sync(c[i][j], g_qbias + nBase + wn * 64 + j * 16, MID,
                                   wmma::mem_row_major);

    for (int k0 = 0; k0 < 512; k0 += 32) {
#pragma unroll
        for (int l = 0; l < 4; l++) {
            int idx = tid + l * 256;
            int kk = idx >> 5;
            int m = (idx & 31) * 4;
            float4 v = *(const float4*)&xb[(size_t)(k0 + kk) * HW + mBase + m];
            As[kk][m]     = __float2half(v.x);
            As[kk][m + 1] = __float2half(v.y);
            As[kk][m + 2] = __float2half(v.z);
            As[kk][m + 3] = __float2half(v.w);
        }
#pragma unroll
        for (int l = 0; l < 2; l++) {
            int idx = tid + l * 256;
            int kk = idx >> 4;
            int n = (idx & 15) * 8;
            *(uint4*)&Bs[kk][n] = *(const uint4*)&g_Wq_h[(k0 + kk) * MID + nBase + n];
        }
        __syncthreads();
#pragma unroll
        for (int ks = 0; ks < 32; ks += 16) {
            wmma::fragment<wmma::matrix_a, 16, 16, 16, __half, wmma::col_major> af[2];
            wmma::fragment<wmma::matrix_b, 16, 16, 16, __half, wmma::row_major> bf[4];
#pragma unroll
            for (int i = 0; i < 2; i++)
                wmma::load_matrix_sync(af[i], &As[ks][wm * 32 + i * 16], 136);
#pragma unroll
            for (int j = 0; j < 4; j++)
                wmma::load_matrix_sync(bf[j], &Bs[ks][wn * 64 + j * 16], 136);
#pragma unroll
            for (int i = 0; i < 2; i++)
#pragma unroll
                for (int j = 0; j < 4; j++)
                    wmma::mma_sync(c[i][j], af[i], bf[j], c[i][j]);
        }
        __syncthreads();
    }
#pragma unroll
    for (int i = 0; i < 2; i++) {
        int row = b * HW + mBase + wm * 32 + i * 16;
#pragma unroll
        for (int j = 0; j < 4; j++) {
            int col = nBase + wn * 64 + j * 16;
            wmma::store_matrix_sync(g_q + (size_t)row * MID + col, c[i][j], MID,
                                    wmma::mem_row_major);
        }
    }
}

// ---------------- 7. fused attention (fp32) -> writes half O ----------------
__global__ void k_att() {
    __shared__ float qs[256][33];
    __shared__ float ls[32][81];
    int id = blockIdx.x;
    int pi = id & 31;
    int bn = id >> 5;
    int b = bn >> 4, n = bn & 15;
    int i0 = (n >> 2) * 32, j0 = (n & 3) * 32;
    int row = i0 + pi;
    int t = threadIdx.x;

    const float* qbase = g_q + ((size_t)b * HW + row * Ww + j0) * MID;
#pragma unroll
    for (int e = t; e < 8192; e += 256) {
        int p = e >> 8, m = e & 255;
        qs[m][p] = qbase[(size_t)p * MID + m];
    }
    __syncthreads();

    const float* kbase = g_kk + (size_t)bn * CMn * MID;
    for (int idx = t; idx < 32 * CMn; idx += 256) {
        int p = idx & 31, c = idx >> 5;
        const float4* k4 = (const float4*)(kbase + c * MID);
        float s = 0.f;
#pragma unroll 8
        for (int m4 = 0; m4 < 64; m4++) {
            float4 kv = k4[m4];
            s += qs[m4 * 4 + 0][p] * kv.x + qs[m4 * 4 + 1][p] * kv.y
               + qs[m4 * 4 + 2][p] * kv.z + qs[m4 * 4 + 3][p] * kv.w;
        }
        ls[p][c] = s;
    }
    __syncthreads();

    {
        int p = t >> 3, lg = t & 7;
        float mx = -1e30f;
        for (int c = lg; c < CMn; c += 8) mx = fmaxf(mx, ls[p][c]);
        for (int o = 4; o > 0; o >>= 1) mx = fmaxf(mx, __shfl_xor_sync(0xffffffffu, mx, o, 8));
        float s = 0.f;
        for (int c = lg; c < CMn; c += 8) { float e = expf(ls[p][c] - mx); ls[p][c] = e; s += e; }
        for (int o = 4; o > 0; o >>= 1) s += __shfl_xor_sync(0xffffffffu, s, o, 8);
        float inv = 1.0f / s;
        for (int c = lg; c < CMn; c += 8) ls[p][c] *= inv;
    }
    __syncthreads();

    float acc[32];
#pragma unroll
    for (int p = 0; p < 32; p++) acc[p] = 0.f;
    for (int c = 0; c < CMn; c++) {
        float vv = g_vv[c * MID + t];
#pragma unroll
        for (int p = 0; p < 32; p++) acc[p] += ls[p][c] * vv;
    }
    __half* ob = g_oh + ((size_t)b * HW + row * Ww + j0) * MID;
#pragma unroll
    for (int p = 0; p < 32; p++) ob[(size_t)p * MID + t] = __float2half(acc[p]);
}

// ---------------- 8. conv (WMMA fp16) + BN + ReLU ----------------
__global__ __launch_bounds__(256, 1) void k_conv_w(const float* __restrict__ gamma,
                                                   const float* __restrict__ beta,
                                                   const float* __restrict__ mean,
                                                   const float* __restrict__ var,
                                                   float* __restrict__ y) {
    __shared__ __align__(16) union {
        struct { __half A[128][40]; __half B[32][72]; } ab;
        float C[64 * 136];
    } u;
    int nBase = blockIdx.x * 64;
    int mBase = blockIdx.y * 128;
    int tid = threadIdx.x;
    int wid = tid >> 5;
    int wm = wid & 3;
    int wn = wid >> 2;

    wmma::fragment<wmma::accumulator, 16, 16, 16, float> c[2][2];
#pragma unroll
    for (int i = 0; i < 2; i++)
#pragma unroll
        for (int j = 0; j < 2; j++) wmma::fill_fragment(c[i][j], 0.f);

    for (int k0 = 0; k0 < 256; k0 += 32) {
#pragma unroll
        for (int l = 0; l < 2; l++) {
            int idx = tid + l * 256;
            int m = idx >> 2;
            int kk = (idx & 3) * 8;
            *(uint4*)&u.ab.A[m][kk] = *(const uint4*)&g_oh[(size_t)(mBase + m) * MID + k0 + kk];
        }
        {
            int kk = tid >> 3;
            int n = (tid & 7) * 8;
            *(uint4*)&u.ab.B[kk][n] = *(const uint4*)&g_Wc_h[(k0 + kk) * Cc + nBase + n];
        }
        __syncthreads();
#pragma unroll
        for (int ks = 0; ks < 32; ks += 16) {
            wmma::fragment<wmma::matrix_a, 16, 16, 16, __half, wmma::row_major> af[2];
            wmma::fragment<wmma::matrix_b, 16, 16, 16, __half, wmma::row_major> bf[2];
#pragma unroll
            for (int i = 0; i < 2; i++)
                wmma::load_matrix_sync(af[i], &u.ab.A[wm * 32 + i * 16][ks], 40);
#pragma unroll
            for (int j = 0; j < 2; j++)
                wmma::load_matrix_sync(bf[j], &u.ab.B[ks][wn * 32 + j * 16], 72);
#pragma unroll
            for (int i = 0; i < 2; i++)
#pragma unroll
                for (int j = 0; j < 2; j++)
                    wmma::mma_sync(c[i][j], af[i], bf[j], c[i][j]);
        }
        __syncthreads();
    }

#pragma unroll
    for (int i = 0; i < 2; i++)
#pragma unroll
        for (int j = 0; j < 2; j++)
            wmma::store_matrix_sync(&u.C[(wn * 32 + j * 16) * 136 + wm * 32 + i * 16],
                                    c[i][j], 136, wmma::mem_col_major);
    __syncthreads();

    {
        int n = tid >> 2;
        int q4 = tid & 3;
        int ch = nBase + n;
        float iv = gamma[ch] / sqrtf(var[ch] + 1e-5f);
        float ad = beta[ch] - mean[ch] * iv;
        int bb = mBase >> 14;
        int pixBase = mBase & 16383;
        float* yrow = y + ((size_t)bb * Cc + ch) * HW + pixBase;
        const float* crow = &u.C[n * 136];
#pragma unroll
        for (int l = 0; l < 8; l++) {
            int m = (q4 + l * 4) * 4;
            float4 v = *(const float4*)&crow[m];
            v.x = fmaxf(v.x * iv + ad, 0.f);
            v.y = fmaxf(v.y * iv + ad, 0.f);
            v.z = fmaxf(v.z * iv + ad, 0.f);
            v.w = fmaxf(v.w * iv + ad, 0.f);
            *(float4*)&yrow[m] = v;
        }
    }
}

// ---------------- launcher ----------------
extern "C" void kernel_launch(void* const* d_in, const int* in_sizes, int n_in,
                              void* d_out, int out_size) {
    const float* x   = (const float*)d_in[0];
    const float* sim = (const float*)d_in[1];
    const float* gcc = (const float*)d_in[2];
    const float* Wq  = (const float*)d_in[3];
    const float* bq  = (const float*)d_in[4];
    const float* Wk  = (const float*)d_in[5];
    const float* bk  = (const float*)d_in[6];
    const float* Wv  = (const float*)d_in[7];
    const float* bv  = (const float*)d_in[8];
    const float* Wc  = (const float*)d_in[9];
    const float* gm  = (const float*)d_in[10];
    const float* bt  = (const float*)d_in[11];
    const float* mn  = (const float*)d_in[12];
    const float* vr  = (const float*)d_in[13];
    float* y = (float*)d_out;
    float* tail = y + (size_t)Bsz * Cc * HW;

    k_setup<<<128, 256>>>(Wq, Wk, Wc, bq);
    k_pool<<<Bsz * CMn * Np, 256>>>(sim, tail);
    k_softmax<<<Bsz * Np * CMn, 256>>>(sim);
    k_local_w<<<dim3(4, 64), 320>>>(x);
    k_kproj_w<<<dim3(2, 64), 320>>>(bk);
    k_v<<<CMn, 256>>>(gcc, Wv, bv);
    k_q_w<<<dim3(2, 128, 4), 256>>>(x);
    k_att<<<2048, 256>>>();
    k_conv_w<<<dim3(8, 512), 256>>>(gm, bt, mn, vr, y);
}

// round 6
// speedup vs baseline: 5.6130x; 2.4385x over previous
#include <cuda_runtime.h>
#include <cuda_fp16.h>
#include <mma.h>
#include <math.h>

using namespace nvcuda;

#define Bsz 4
#define Cc 512
#define MID 256
#define CMn 76
#define Hh 128
#define Ww 128
#define HW 16384
#define Pp 1024
#define Np 16

// ---------------- static scratch ----------------
__device__ float  g_pool[Bsz * CMn * Np];
__device__ __half g_smxh[(size_t)64 * 80 * 1024];       // softmax(sim), padded 80 rows
__device__ __half g_localh[(size_t)64 * 80 * 512];      // local (conf folded), padded
__device__ __half g_kkh[(size_t)64 * 76 * 256];         // k proj (half)
__device__ __half g_vvh[76 * 256];                      // v proj (half)
__device__ float  g_q[(size_t)64 * 1024 * 256];         // q fp32, PATCH-major [bn][p][m]
__device__ float  g_o[(size_t)64 * 1024 * 256];         // attn out fp32, patch-major
__device__ __half g_xh[(size_t)Bsz * Cc * HW];          // x as half
__device__ __half g_Wq_h[Cc * MID];
__device__ __half g_Wk_h[Cc * MID];
__device__ __half g_Wc_h[MID * Cc];
__device__ float  g_qbias[16 * MID];

// ---------------- cp.async helpers ----------------
__device__ __forceinline__ void cp16(void* dst, const void* src) {
    unsigned d = (unsigned)__cvta_generic_to_shared(dst);
    asm volatile("cp.async.ca.shared.global [%0], [%1], 16;\n" :: "r"(d), "l"(src));
}
__device__ __forceinline__ void cp_commit() { asm volatile("cp.async.commit_group;\n"); }
template <int N>
__device__ __forceinline__ void cp_wait() { asm volatile("cp.async.wait_group %0;\n" :: "n"(N)); }

// ---------------- 0. setup ----------------
__global__ void k_setup(const float* __restrict__ Wq, const float* __restrict__ Wk,
                        const float* __restrict__ Wc, const float* __restrict__ bq) {
    int t = blockIdx.x * blockDim.x + threadIdx.x;
    int stride = gridDim.x * blockDim.x;
    for (int i = t; i < Cc * MID; i += stride) {
        g_Wq_h[i] = __float2half(Wq[i]);
        g_Wk_h[i] = __float2half(Wk[i]);
        g_Wc_h[i] = __float2half(Wc[i]);
    }
    for (int i = t; i < 16 * MID; i += stride) g_qbias[i] = bq[i & (MID - 1)];
    // zero pad rows 76..79 of smxh / localh (contiguous per bn)
    for (int i = t; i < 64 * 4 * 1024; i += stride) {
        int bn = i >> 12, rem = i & 4095;
        g_smxh[((size_t)bn * 80 + 76) * 1024 + rem] = __float2half(0.f);
    }
    for (int i = t; i < 64 * 4 * 512; i += stride) {
        int bn = i >> 11, rem = i & 2047;
        g_localh[((size_t)bn * 80 + 76) * 512 + rem] = __float2half(0.f);
    }
}

// ---------------- 0b. x -> half ----------------
__global__ void k_xh(const float* __restrict__ x) {
    size_t n8 = (size_t)Bsz * Cc * HW / 8;
    for (size_t g = blockIdx.x * (size_t)blockDim.x + threadIdx.x; g < n8;
         g += (size_t)gridDim.x * blockDim.x) {
        const float4* s = (const float4*)x + g * 2;
        float4 a = s[0], b = s[1];
        __half2 h0 = __floats2half2_rn(a.x, a.y);
        __half2 h1 = __floats2half2_rn(a.z, a.w);
        __half2 h2 = __floats2half2_rn(b.x, b.y);
        __half2 h3 = __floats2half2_rn(b.z, b.w);
        uint4 o;
        o.x = *(unsigned*)&h0; o.y = *(unsigned*)&h1;
        o.z = *(unsigned*)&h2; o.w = *(unsigned*)&h3;
        ((uint4*)g_xh)[g] = o;
    }
}

// ---------------- 1+2. fused pool + softmax ----------------
// grid 4864 = bn*76 + cm, block 256
__global__ void k_poolsm(const float* __restrict__ sim, float* __restrict__ out_tail) {
    int id = blockIdx.x;
    int cm = id % CMn;
    int bn = id / CMn;
    int n = bn & 15, b = bn >> 4;
    int i0 = (n >> 2) * 32, j0 = (n & 3) * 32;
    const float* base = sim + ((size_t)b * CMn + cm) * HW;
    int t = threadIdx.x;
    float v[4];
    float mx = -1e30f, sraw = 0.f;
#pragma unroll
    for (int it = 0; it < 4; it++) {
        int p = t + it * 256;
        int pi = p >> 5, pj = p & 31;
        v[it] = base[(i0 + pi) * Ww + j0 + pj];
        mx = fmaxf(mx, v[it]);
        sraw += v[it];
    }
    __shared__ float red[256];
    // raw sum -> pool
    red[t] = sraw; __syncthreads();
    for (int o = 128; o > 0; o >>= 1) {
        if (t < o) red[t] += red[t + o];
        __syncthreads();
    }
    if (t == 0) {
        float m = red[0] * (1.0f / 1024.0f);
        int pid = (b * CMn + cm) * 16 + n;
        g_pool[pid] = m;
        out_tail[pid] = m;
    }
    __syncthreads();
    // max
    red[t] = mx; __syncthreads();
    for (int o = 128; o > 0; o >>= 1) {
        if (t < o) red[t] = fmaxf(red[t], red[t + o]);
        __syncthreads();
    }
    float gmx = red[0]; __syncthreads();
    float s = 0.f;
#pragma unroll
    for (int it = 0; it < 4; it++) { v[it] = expf(v[it] - gmx); s += v[it]; }
    red[t] = s; __syncthreads();
    for (int o = 128; o > 0; o >>= 1) {
        if (t < o) red[t] += red[t + o];
        __syncthreads();
    }
    float inv = 1.0f / red[0];
    __half* dst = g_smxh + ((size_t)bn * 80 + cm) * Pp;
#pragma unroll
    for (int it = 0; it < 4; it++) { int p = t + it * 256; dst[p] = __float2half(v[it] * inv); }
}

// ---------------- 3. local = smx^T @ xs * conf  (WMMA, cp.async x2) --------
// grid (4 ntiles, 64 bn), 320 threads = 10 warps (5M x 2N)
__device__ __forceinline__ void local_stage(int tid, __half* Adst, __half* Bdst,
                                            const __half* Asrc, const __half* Bsrc,
                                            int it, int nBase, int baseoff) {
    for (int idx = tid; idx < 832; idx += 320) {
        if (idx < 320) {
            int row = idx >> 2, col = (idx & 3) * 8;
            cp16(Adst + row * 40 + col, Asrc + (size_t)row * 1024 + it * 32 + col);
        } else {
            int j = idx - 320;
            int row = j >> 2, col = (j & 3) * 8;
            cp16(Bdst + row * 40 + col,
                 Bsrc + (size_t)(nBase + row) * HW + baseoff + it * Ww + col);
        }
    }
    cp_commit();
}

__global__ __launch_bounds__(320, 2) void k_local_w() {
    __shared__ __align__(16) union {
        struct { __half A[2][80][40]; __half B[2][128][40]; } s;
        float C[80 * 136];
    } u;
    int bn = blockIdx.y;
    int b = bn >> 4, np = bn & 15;
    int i0 = (np >> 2) * 32, j0 = (np & 3) * 32;
    int baseoff = i0 * Ww + j0;
    int nBase = blockIdx.x * 128;
    const __half* Asrc = g_smxh + (size_t)bn * 80 * 1024;
    const __half* Bsrc = g_xh + (size_t)b * Cc * HW;
    int tid = threadIdx.x;
    int wid = tid >> 5;
    int wm = wid % 5, wn = wid / 5;

    wmma::fragment<wmma::accumulator, 16, 16, 16, float> c[4];
#pragma unroll
    for (int j = 0; j < 4; j++) wmma::fill_fragment(c[j], 0.f);

    local_stage(tid, &u.s.A[0][0][0], &u.s.B[0][0][0], Asrc, Bsrc, 0, nBase, baseoff);
    for (int it = 0; it < 32; it++) {
        if (it + 1 < 32) {
            int s2 = (it + 1) & 1;
            local_stage(tid, &u.s.A[s2][0][0], &u.s.B[s2][0][0], Asrc, Bsrc, it + 1, nBase, baseoff);
            cp_wait<1>();
        } else {
            cp_wait<0>();
        }
        __syncthreads();
        int s = it & 1;
#pragma unroll
        for (int ks = 0; ks < 32; ks += 16) {
            wmma::fragment<wmma::matrix_a, 16, 16, 16, __half, wmma::row_major> af;
            wmma::load_matrix_sync(af, &u.s.A[s][wm * 16][ks], 40);
#pragma unroll
            for (int j = 0; j < 4; j++) {
                wmma::fragment<wmma::matrix_b, 16, 16, 16, __half, wmma::col_major> bf;
                wmma::load_matrix_sync(bf, &u.s.B[s][wn * 64 + j * 16][ks], 40);
                wmma::mma_sync(c[j], af, bf, c[j]);
            }
        }
        __syncthreads();
    }
#pragma unroll
    for (int j = 0; j < 4; j++)
        wmma::store_matrix_sync(&u.C[(wm * 16) * 136 + wn * 64 + j * 16], c[j], 136,
                                wmma::mem_row_major);
    __syncthreads();
    for (int idx = tid; idx < 76 * 128; idx += 320) {
        int cc = idx >> 7, nn = idx & 127;
        float conf = g_pool[(b * CMn + cc) * 16 + np];
        g_localh[((size_t)bn * 80 + cc) * 512 + nBase + nn] =
            __float2half(u.C[cc * 136 + nn] * conf);
    }
}

// ---------------- 4. k = local @ Wk + bk (WMMA, half out) ----------------
__global__ __launch_bounds__(320, 2) void k_kproj_w(const float* __restrict__ bk) {
    __shared__ __align__(16) union {
        struct { __half A[80][40]; __half B[32][136]; } ab;
        float C[80 * 136];
    } u;
    int bn = blockIdx.y;
    int nBase = blockIdx.x * 128;
    const __half* Ap = g_localh + (size_t)bn * 80 * 512;
    int tid = threadIdx.x;
    int wid = tid >> 5;
    int wm = wid % 5, wn = wid / 5;

    wmma::fragment<wmma::accumulator, 16, 16, 16, float> c[4];
#pragma unroll
    for (int j = 0; j < 4; j++) wmma::fill_fragment(c[j], 0.f);

    for (int k0 = 0; k0 < 512; k0 += 32) {
        {
            int cc = tid >> 2;
            int h8 = (tid & 3) * 8;
            *(uint4*)&u.ab.A[cc][h8] = *(const uint4*)&Ap[(size_t)cc * 512 + k0 + h8];
        }
        for (int idx = tid; idx < 512; idx += 320) {
            int kk = idx >> 4;
            int nn = (idx & 15) * 8;
            *(uint4*)&u.ab.B[kk][nn] = *(const uint4*)&g_Wk_h[(k0 + kk) * MID + nBase + nn];
        }
        __syncthreads();
#pragma unroll
        for (int ks = 0; ks < 32; ks += 16) {
            wmma::fragment<wmma::matrix_a, 16, 16, 16, __half, wmma::row_major> af;
            wmma::load_matrix_sync(af, &u.ab.A[wm * 16][ks], 40);
#pragma unroll
            for (int j = 0; j < 4; j++) {
                wmma::fragment<wmma::matrix_b, 16, 16, 16, __half, wmma::row_major> bf;
                wmma::load_matrix_sync(bf, &u.ab.B[ks][wn * 64 + j * 16], 136);
                wmma::mma_sync(c[j], af, bf, c[j]);
            }
        }
        __syncthreads();
    }
#pragma unroll
    for (int j = 0; j < 4; j++)
        wmma::store_matrix_sync(&u.C[(wm * 16) * 136 + wn * 64 + j * 16], c[j], 136,
                                wmma::mem_row_major);
    __syncthreads();
    for (int idx = tid; idx < 76 * 128; idx += 320) {
        int cc = idx >> 7, nn = idx & 127;
        g_kkh[((size_t)bn * 76 + cc) * 256 + nBase + nn] =
            __float2half(u.C[cc * 136 + nn] + bk[nBase + nn]);
    }
}

// ---------------- 5. v = g @ Wv + bv (half out) ----------------
__global__ void k_v(const float* __restrict__ g, const float* __restrict__ Wv,
                    const float* __restrict__ bv) {
    __shared__ float sg[512];
    int c = blockIdx.x, t = threadIdx.x;
    for (int k = t; k < 512; k += 256) sg[k] = g[c * 512 + k];
    __syncthreads();
    float acc = 0.f;
    for (int k = 0; k < 512; k++) acc += sg[k] * Wv[k * MID + t];
    g_vvh[c * MID + t] = __float2half(acc + bv[t]);
}

// ---------------- 6. q = x^T @ Wq + bq  (WMMA, cp.async x2, patch-major out)
__device__ __forceinline__ void q_stage(int tid, __half* Adst, __half* Bdst,
                                        const __half* xb, int k0, int mBase, int nBase) {
#pragma unroll
    for (int l = 0; l < 4; l++) {
        int idx = tid + l * 256;
        if (idx < 512) {
            int kk = idx >> 4, m = (idx & 15) * 8;
            cp16(Adst + kk * 136 + m, xb + (size_t)(k0 + kk) * HW + mBase + m);
        } else {
            int j = idx - 512;
            int kk = j >> 4, n = (j & 15) * 8;
            cp16(Bdst + kk * 136 + n, g_Wq_h + (k0 + kk) * MID + nBase + n);
        }
    }
    cp_commit();
}

__global__ __launch_bounds__(256, 2) void k_q_w() {
    __shared__ __align__(16) __half As[2][32][136];
    __shared__ __align__(16) __half Bs[2][32][136];
    int b = blockIdx.z;
    int r = blockIdx.y;                 // image row
    int mBase = r * 128;
    int nBase = blockIdx.x * 128;
    const __half* xb = g_xh + (size_t)b * Cc * HW;
    int tid = threadIdx.x;
    int wid = tid >> 5;
    int wm = wid & 3;
    int wn = wid >> 2;

    wmma::fragment<wmma::accumulator, 16, 16, 16, float> c[2][4];
#pragma unroll
    for (int i = 0; i < 2; i++)
#pragma unroll
        for (int j = 0; j < 4; j++)
            wmma::load_matrix_sync(c[i][j], g_qbias + nBase + wn * 64 + j * 16, MID,
                                   wmma::mem_row_major);

    q_stage(tid, &As[0][0][0], &Bs[0][0][0], xb, 0, mBase, nBase);
    for (int it = 0; it < 16; it++) {
        if (it + 1 < 16) {
            int s2 = (it + 1) & 1;
            q_stage(tid, &As[s2][0][0], &Bs[s2][0][0], xb, (it + 1) * 32, mBase, nBase);
            cp_wait<1>();
        } else {
            cp_wait<0>();
        }
        __syncthreads();
        int s = it & 1;
#pragma unroll
        for (int ks = 0; ks < 32; ks += 16) {
            wmma::fragment<wmma::matrix_a, 16, 16, 16, __half, wmma::col_major> af[2];
            wmma::fragment<wmma::matrix_b, 16, 16, 16, __half, wmma::row_major> bf[4];
#pragma unroll
            for (int i = 0; i < 2; i++)
                wmma::load_matrix_sync(af[i], &As[s][ks][wm * 32 + i * 16], 136);
#pragma unroll
            for (int j = 0; j < 4; j++)
                wmma::load_matrix_sync(bf[j], &Bs[s][ks][wn * 64 + j * 16], 136);
#pragma unroll
            for (int i = 0; i < 2; i++)
#pragma unroll
                for (int j = 0; j < 4; j++)
                    wmma::mma_sync(c[i][j], af[i], bf[j], c[i][j]);
        }
        __syncthreads();
    }
    // patch-major store: warp wm covers patch column wm of this image row
    int bn = b * 16 + (r >> 5) * 4 + wm;
    int prow = r & 31;
#pragma unroll
    for (int i = 0; i < 2; i++) {
        size_t rowbase = (size_t)bn * 1024 + prow * 32 + i * 16;
#pragma unroll
        for (int j = 0; j < 4; j++) {
            wmma::store_matrix_sync(g_q + rowbase * 256 + nBase + wn * 64 + j * 16,
                                    c[i][j], 256, wmma::mem_row_major);
        }
    }
}

// ---------------- 7. attention (WMMA): S=QK^T, softmax, O=PV ----------------
// grid (16 mtiles, 64 bn), 256 threads (4M x 2N warps), M-tile 64
__global__ __launch_bounds__(256, 2) void k_att_w() {
    __shared__ __align__(16) union {
        struct { __half Q[64][72]; __half K[80][72]; } a;
        __half P[64][88];
    } uA;
    __shared__ __align__(16) union {
        float S[64][92];
        __half V[80][136];
    } uB;
    int bn = blockIdx.y;
    int mBase = blockIdx.x * 64;
    int tid = threadIdx.x;
    int wid = tid >> 5;
    int wm = wid & 3;
    int wn = wid >> 2;
    const float* qsrc = g_q + ((size_t)bn * 1024 + mBase) * 256;
    const __half* ksrc = g_kkh + (size_t)bn * 76 * 256;

    int nfr = (wn == 0) ? 3 : 2;
    int nb0 = (wn == 0) ? 0 : 48;
    wmma::fragment<wmma::accumulator, 16, 16, 16, float> sacc[3];
#pragma unroll
    for (int f = 0; f < 3; f++) wmma::fill_fragment(sacc[f], 0.f);

    for (int k0 = 0; k0 < 256; k0 += 64) {
        // stage Q (fp32 -> half)
#pragma unroll
        for (int l = 0; l < 4; l++) {
            int idx = tid + l * 256;
            int row = idx >> 4, c4 = (idx & 15) * 4;
            float4 v = *(const float4*)&qsrc[(size_t)row * 256 + k0 + c4];
            uA.a.Q[row][c4]     = __float2half(v.x);
            uA.a.Q[row][c4 + 1] = __float2half(v.y);
            uA.a.Q[row][c4 + 2] = __float2half(v.z);
            uA.a.Q[row][c4 + 3] = __float2half(v.w);
        }
        // stage K (80 rows, pad zero)
        for (int idx = tid; idx < 640; idx += 256) {
            int row = idx >> 3, c8 = (idx & 7) * 8;
            uint4 z = {0, 0, 0, 0};
            uint4 val = (row < 76) ? *(const uint4*)&ksrc[(size_t)row * 256 + k0 + c8] : z;
            *(uint4*)&uA.a.K[row][c8] = val;
        }
        __syncthreads();
#pragma unroll
        for (int ks = 0; ks < 64; ks += 16) {
            wmma::fragment<wmma::matrix_a, 16, 16, 16, __half, wmma::row_major> af;
            wmma::load_matrix_sync(af, &uA.a.Q[wm * 16][ks], 72);
            for (int f = 0; f < nfr; f++) {
                wmma::fragment<wmma::matrix_b, 16, 16, 16, __half, wmma::col_major> bf;
                wmma::load_matrix_sync(bf, &uA.a.K[nb0 + f * 16][ks], 72);
                wmma::mma_sync(sacc[f], af, bf, sacc[f]);
            }
        }
        __syncthreads();
    }
    for (int f = 0; f < nfr; f++)
        wmma::store_matrix_sync(&uB.S[wm * 16][nb0 + f * 16], sacc[f], 92,
                                wmma::mem_row_major);
    __syncthreads();

    // softmax over c (rows handled by first 64 threads); P overlays Q/K
    if (tid < 64) {
        float mx = -1e30f;
        for (int c = 0; c < 76; c++) mx = fmaxf(mx, uB.S[tid][c]);
        float s = 0.f;
        for (int c = 0; c < 76; c++) {
            float e = expf(uB.S[tid][c] - mx);
            uB.S[tid][c] = e;
            s += e;
        }
        float inv = 1.0f / s;
        for (int c = 0; c < 76; c++) uA.P[tid][c] = __float2half(uB.S[tid][c] * inv);
        uA.P[tid][76] = __float2half(0.f);
        uA.P[tid][77] = __float2half(0.f);
        uA.P[tid][78] = __float2half(0.f);
        uA.P[tid][79] = __float2half(0.f);
    }
    __syncthreads();

    // O = P @ V, two 128-col halves; V overlays S
    for (int hb = 0; hb < 2; hb++) {
        for (int idx = tid; idx < 1280; idx += 256) {
            int row = idx >> 4, c8 = (idx & 15) * 8;
            uint4 z = {0, 0, 0, 0};
            uint4 val = (row < 76) ? *(const uint4*)&g_vvh[row * 256 + hb * 128 + c8] : z;
            *(uint4*)&uB.V[row][c8] = val;
        }
        __syncthreads();
        wmma::fragment<wmma::accumulator, 16, 16, 16, float> oacc[4];
#pragma unroll
        for (int j = 0; j < 4; j++) wmma::fill_fragment(oacc[j], 0.f);
#pragma unroll
        for (int kc = 0; kc < 5; kc++) {
            int ks = kc * 16;
            wmma::fragment<wmma::matrix_a, 16, 16, 16, __half, wmma::row_major> pf;
            wmma::load_matrix_sync(pf, &uA.P[wm * 16][ks], 88);
#pragma unroll
            for (int j = 0; j < 4; j++) {
                wmma::fragment<wmma::matrix_b, 16, 16, 16, __half, wmma::row_major> vf;
                wmma::load_matrix_sync(vf, &uB.V[ks][wn * 64 + j * 16], 136);
                wmma::mma_sync(oacc[j], pf, vf, oacc[j]);
            }
        }
        float* obase = g_o + ((size_t)bn * 1024 + mBase + wm * 16) * 256 + hb * 128 + wn * 64;
#pragma unroll
        for (int j = 0; j < 4; j++)
            wmma::store_matrix_sync(obase + j * 16, oacc[j], 256, wmma::mem_row_major);
        __syncthreads();
    }
}

// ---------------- 8. conv (WMMA) + BN + ReLU, patch-major A ----------------
__global__ __launch_bounds__(256, 2) void k_conv_w(const float* __restrict__ gamma,
                                                   const float* __restrict__ beta,
                                                   const float* __restrict__ mean,
                                                   const float* __restrict__ var,
                                                   float* __restrict__ y) {
    __shared__ __align__(16) union {
        struct { __half A[128][40]; __half B[32][72]; } ab;
        float C[64 * 136];
    } u;
    int nBase = blockIdx.x * 64;
    int mBase = blockIdx.y * 128;
    int tid = threadIdx.x;
    int wid = tid >> 5;
    int wm = wid & 3;
    int wn = wid >> 2;

    wmma::fragment<wmma::accumulator, 16, 16, 16, float> c[2][2];
#pragma unroll
    for (int i = 0; i < 2; i++)
#pragma unroll
        for (int j = 0; j < 2; j++) wmma::fill_fragment(c[i][j], 0.f);

    for (int k0 = 0; k0 < 256; k0 += 32) {
        // A: 128 x 32 fp32 -> half (1024 float4)
#pragma unroll
        for (int l = 0; l < 4; l++) {
            int idx = tid + l * 256;
            int m = idx >> 3;
            int kf = (idx & 7) * 4;
            float4 v = *(const float4*)&g_o[(size_t)(mBase + m) * 256 + k0 + kf];
            u.ab.A[m][kf]     = __float2half(v.x);
            u.ab.A[m][kf + 1] = __float2half(v.y);
            u.ab.A[m][kf + 2] = __float2half(v.z);
            u.ab.A[m][kf + 3] = __float2half(v.w);
        }
        {
            int kk = tid >> 3;
            int n = (tid & 7) * 8;
            *(uint4*)&u.ab.B[kk][n] = *(const uint4*)&g_Wc_h[(k0 + kk) * Cc + nBase + n];
        }
        __syncthreads();
#pragma unroll
        for (int ks = 0; ks < 32; ks += 16) {
            wmma::fragment<wmma::matrix_a, 16, 16, 16, __half, wmma::row_major> af[2];
            wmma::fragment<wmma::matrix_b, 16, 16, 16, __half, wmma::row_major> bf[2];
#pragma unroll
            for (int i = 0; i < 2; i++)
                wmma::load_matrix_sync(af[i], &u.ab.A[wm * 32 + i * 16][ks], 40);
#pragma unroll
            for (int j = 0; j < 2; j++)
                wmma::load_matrix_sync(bf[j], &u.ab.B[ks][wn * 32 + j * 16], 72);
#pragma unroll
            for (int i = 0; i < 2; i++)
#pragma unroll
                for (int j = 0; j < 2; j++)
                    wmma::mma_sync(c[i][j], af[i], bf[j], c[i][j]);
        }
        __syncthreads();
    }

#pragma unroll
    for (int i = 0; i < 2; i++)
#pragma unroll
        for (int j = 0; j < 2; j++)
            wmma::store_matrix_sync(&u.C[(wn * 32 + j * 16) * 136 + wm * 32 + i * 16],
                                    c[i][j], 136, wmma::mem_col_major);
    __syncthreads();

    {
        int n = tid >> 2;
        int q4 = tid & 3;
        int ch = nBase + n;
        float iv = gamma[ch] / sqrtf(var[ch] + 1e-5f);
        float ad = beta[ch] - mean[ch] * iv;
        // patch-major rows: mBase = bn*1024 + pp0
        int bn = mBase >> 10;
        int pp0 = mBase & 1023;
        int b = bn >> 4, np = bn & 15;
        int i0 = (np >> 2) * 32, j0 = (np & 3) * 32;
        float* ybase = y + ((size_t)b * Cc + ch) * HW;
        const float* crow = &u.C[n * 136];
#pragma unroll
        for (int l = 0; l < 8; l++) {
            int m = (q4 + l * 4) * 4;
            int p = pp0 + m;
            float4 v = *(const float4*)&crow[m];
            v.x = fmaxf(v.x * iv + ad, 0.f);
            v.y = fmaxf(v.y * iv + ad, 0.f);
            v.z = fmaxf(v.z * iv + ad, 0.f);
            v.w = fmaxf(v.w * iv + ad, 0.f);
            *(float4*)&ybase[(i0 + (p >> 5)) * 128 + j0 + (p & 31)] = v;
        }
    }
}

// ---------------- launcher ----------------
extern "C" void kernel_launch(void* const* d_in, const int* in_sizes, int n_in,
                              void* d_out, int out_size) {
    const float* x   = (const float*)d_in[0];
    const float* sim = (const float*)d_in[1];
    const float* gcc = (const float*)d_in[2];
    const float* Wq  = (const float*)d_in[3];
    const float* bq  = (const float*)d_in[4];
    const float* Wk  = (const float*)d_in[5];
    const float* bk  = (const float*)d_in[6];
    const float* Wv  = (const float*)d_in[7];
    const float* bv  = (const float*)d_in[8];
    const float* Wc  = (const float*)d_in[9];
    const float* gm  = (const float*)d_in[10];
    const float* bt  = (const float*)d_in[11];
    const float* mn  = (const float*)d_in[12];
    const float* vr  = (const float*)d_in[13];
    float* y = (float*)d_out;
    float* tail = y + (size_t)Bsz * Cc * HW;

    k_setup<<<256, 256>>>(Wq, Wk, Wc, bq);
    k_xh<<<8192, 256>>>(x);
    k_poolsm<<<Bsz * Np * CMn, 256>>>(sim, tail);
    k_local_w<<<dim3(4, 64), 320>>>();
    k_kproj_w<<<dim3(2, 64), 320>>>(bk);
    k_v<<<CMn, 256>>>(gcc, Wv, bv);
    k_q_w<<<dim3(2, 128, 4), 256>>>();
    k_att_w<<<dim3(16, 64), 256>>>();
    k_conv_w<<<dim3(8, 512), 256>>>(gm, bt, mn, vr, y);
}

// round 10
// speedup vs baseline: 5.9322x; 1.0569x over previous
#include <cuda_runtime.h>
#include <cuda_fp16.h>
#include <mma.h>
#include <math.h>

using namespace nvcuda;

#define Bsz 4
#define Cc 512
#define MID 256
#define CMn 76
#define Hh 128
#define Ww 128
#define HW 16384
#define Pp 1024
#define Np 16

// ---------------- static scratch ----------------
__device__ float  g_pool[Bsz * CMn * Np];
__device__ __half g_smxh[(size_t)64 * 80 * 1024];       // softmax(sim), padded 80 rows
__device__ __half g_localh[(size_t)64 * 80 * 512];      // local (conf folded), padded
__device__ __half g_kkh[(size_t)64 * 76 * 256];         // k proj (half)
__device__ __half g_vvh[76 * 256];                      // v proj (half)
__device__ __half g_qh[(size_t)64 * 1024 * 256];        // q HALF, patch-major [bn][p][m]
__device__ __half g_oh[(size_t)64 * 1024 * 256];        // attn out HALF, patch-major
__device__ __half g_xh[(size_t)Bsz * Cc * HW];          // x as half
__device__ __half g_Wq_h[Cc * MID];
__device__ __half g_Wk_h[Cc * MID];
__device__ __half g_Wc_h[MID * Cc];
__device__ float  g_qbias[16 * MID];

// ---------------- cp.async helpers ----------------
__device__ __forceinline__ void cp16(void* dst, const void* src) {
    unsigned d = (unsigned)__cvta_generic_to_shared(dst);
    asm volatile("cp.async.ca.shared.global [%0], [%1], 16;\n" :: "r"(d), "l"(src));
}
__device__ __forceinline__ void cp_commit() { asm volatile("cp.async.commit_group;\n"); }
template <int N>
__device__ __forceinline__ void cp_wait() { asm volatile("cp.async.wait_group %0;\n" :: "n"(N)); }

// convert a 16x16 fp32 warp scratch tile (ld=20) to half and write to global.
// caller must __syncwarp() between the scratch store and this call.
__device__ __forceinline__ void scr_to_half(const float* scr, __half* gdst, int ldg, int lane) {
    int rr = lane >> 1, c8 = (lane & 1) * 8;
    const float* s = scr + rr * 20 + c8;
    __half2 h0 = __floats2half2_rn(s[0], s[1]);
    __half2 h1 = __floats2half2_rn(s[2], s[3]);
    __half2 h2 = __floats2half2_rn(s[4], s[5]);
    __half2 h3 = __floats2half2_rn(s[6], s[7]);
    uint4 o;
    o.x = *(unsigned*)&h0; o.y = *(unsigned*)&h1;
    o.z = *(unsigned*)&h2; o.w = *(unsigned*)&h3;
    *(uint4*)(gdst + (size_t)rr * ldg + c8) = o;
}

// ---------------- 0. setup ----------------
__global__ void k_setup(const float* __restrict__ Wq, const float* __restrict__ Wk,
                        const float* __restrict__ Wc, const float* __restrict__ bq) {
    int t = blockIdx.x * blockDim.x + threadIdx.x;
    int stride = gridDim.x * blockDim.x;
    for (int i = t; i < Cc * MID; i += stride) {
        g_Wq_h[i] = __float2half(Wq[i]);
        g_Wk_h[i] = __float2half(Wk[i]);
        g_Wc_h[i] = __float2half(Wc[i]);
    }
    for (int i = t; i < 16 * MID; i += stride) g_qbias[i] = bq[i & (MID - 1)];
    for (int i = t; i < 64 * 4 * 1024; i += stride) {
        int bn = i >> 12, rem = i & 4095;
        g_smxh[((size_t)bn * 80 + 76) * 1024 + rem] = __float2half(0.f);
    }
    for (int i = t; i < 64 * 4 * 512; i += stride) {
        int bn = i >> 11, rem = i & 2047;
        g_localh[((size_t)bn * 80 + 76) * 512 + rem] = __float2half(0.f);
    }
}

// ---------------- 0b. x -> half ----------------
__global__ void k_xh(const float* __restrict__ x) {
    size_t n8 = (size_t)Bsz * Cc * HW / 8;
    for (size_t g = blockIdx.x * (size_t)blockDim.x + threadIdx.x; g < n8;
         g += (size_t)gridDim.x * blockDim.x) {
        const float4* s = (const float4*)x + g * 2;
        float4 a = s[0], b = s[1];
        __half2 h0 = __floats2half2_rn(a.x, a.y);
        __half2 h1 = __floats2half2_rn(a.z, a.w);
        __half2 h2 = __floats2half2_rn(b.x, b.y);
        __half2 h3 = __floats2half2_rn(b.z, b.w);
        uint4 o;
        o.x = *(unsigned*)&h0; o.y = *(unsigned*)&h1;
        o.z = *(unsigned*)&h2; o.w = *(unsigned*)&h3;
        ((uint4*)g_xh)[g] = o;
    }
}

// ---------------- 1+2. fused pool + softmax ----------------
__global__ void k_poolsm(const float* __restrict__ sim, float* __restrict__ out_tail) {
    int id = blockIdx.x;
    int cm = id % CMn;
    int bn = id / CMn;
    int n = bn & 15, b = bn >> 4;
    int i0 = (n >> 2) * 32, j0 = (n & 3) * 32;
    const float* base = sim + ((size_t)b * CMn + cm) * HW;
    int t = threadIdx.x;
    float v[4];
    float mx = -1e30f, sraw = 0.f;
#pragma unroll
    for (int it = 0; it < 4; it++) {
        int p = t + it * 256;
        int pi = p >> 5, pj = p & 31;
        v[it] = base[(i0 + pi) * Ww + j0 + pj];
        mx = fmaxf(mx, v[it]);
        sraw += v[it];
    }
    __shared__ float red[256];
    red[t] = sraw; __syncthreads();
    for (int o = 128; o > 0; o >>= 1) {
        if (t < o) red[t] += red[t + o];
        __syncthreads();
    }
    if (t == 0) {
        float m = red[0] * (1.0f / 1024.0f);
        int pid = (b * CMn + cm) * 16 + n;
        g_pool[pid] = m;
        out_tail[pid] = m;
    }
    __syncthreads();
    red[t] = mx; __syncthreads();
    for (int o = 128; o > 0; o >>= 1) {
        if (t < o) red[t] = fmaxf(red[t], red[t + o]);
        __syncthreads();
    }
    float gmx = red[0]; __syncthreads();
    float s = 0.f;
#pragma unroll
    for (int it = 0; it < 4; it++) { v[it] = expf(v[it] - gmx); s += v[it]; }
    red[t] = s; __syncthreads();
    for (int o = 128; o > 0; o >>= 1) {
        if (t < o) red[t] += red[t + o];
        __syncthreads();
    }
    float inv = 1.0f / red[0];
    __half* dst = g_smxh + ((size_t)bn * 80 + cm) * Pp;
#pragma unroll
    for (int it = 0; it < 4; it++) { int p = t + it * 256; dst[p] = __float2half(v[it] * inv); }
}

// ---------------- 3. local = smx^T @ xs * conf  (WMMA, cp.async x2) --------
__device__ __forceinline__ void local_stage(int tid, __half* Adst, __half* Bdst,
                                            const __half* Asrc, const __half* Bsrc,
                                            int it, int nBase, int baseoff) {
    for (int idx = tid; idx < 832; idx += 320) {
        if (idx < 320) {
            int row = idx >> 2, col = (idx & 3) * 8;
            cp16(Adst + row * 40 + col, Asrc + (size_t)row * 1024 + it * 32 + col);
        } else {
            int j = idx - 320;
            int row = j >> 2, col = (j & 3) * 8;
            cp16(Bdst + row * 40 + col,
                 Bsrc + (size_t)(nBase + row) * HW + baseoff + it * Ww + col);
        }
    }
    cp_commit();
}

__global__ __launch_bounds__(320, 2) void k_local_w() {
    __shared__ __align__(16) union {
        struct { __half A[2][80][40]; __half B[2][128][40]; } s;
        float C[80 * 136];
    } u;
    int bn = blockIdx.y;
    int b = bn >> 4, np = bn & 15;
    int i0 = (np >> 2) * 32, j0 = (np & 3) * 32;
    int baseoff = i0 * Ww + j0;
    int nBase = blockIdx.x * 128;
    const __half* Asrc = g_smxh + (size_t)bn * 80 * 1024;
    const __half* Bsrc = g_xh + (size_t)b * Cc * HW;
    int tid = threadIdx.x;
    int wid = tid >> 5;
    int wm = wid % 5, wn = wid / 5;

    wmma::fragment<wmma::accumulator, 16, 16, 16, float> c[4];
#pragma unroll
    for (int j = 0; j < 4; j++) wmma::fill_fragment(c[j], 0.f);

    local_stage(tid, &u.s.A[0][0][0], &u.s.B[0][0][0], Asrc, Bsrc, 0, nBase, baseoff);
    for (int it = 0; it < 32; it++) {
        if (it + 1 < 32) {
            int s2 = (it + 1) & 1;
            local_stage(tid, &u.s.A[s2][0][0], &u.s.B[s2][0][0], Asrc, Bsrc, it + 1, nBase, baseoff);
            cp_wait<1>();
        } else {
            cp_wait<0>();
        }
        __syncthreads();
        int s = it & 1;
#pragma unroll
        for (int ks = 0; ks < 32; ks += 16) {
            wmma::fragment<wmma::matrix_a, 16, 16, 16, __half, wmma::row_major> af;
            wmma::load_matrix_sync(af, &u.s.A[s][wm * 16][ks], 40);
#pragma unroll
            for (int j = 0; j < 4; j++) {
                wmma::fragment<wmma::matrix_b, 16, 16, 16, __half, wmma::col_major> bf;
                wmma::load_matrix_sync(bf, &u.s.B[s][wn * 64 + j * 16][ks], 40);
                wmma::mma_sync(c[j], af, bf, c[j]);
            }
        }
        __syncthreads();
    }
#pragma unroll
    for (int j = 0; j < 4; j++)
        wmma::store_matrix_sync(&u.C[(wm * 16) * 136 + wn * 64 + j * 16], c[j], 136,
                                wmma::mem_row_major);
    __syncthreads();
    for (int idx = tid; idx < 76 * 128; idx += 320) {
        int cc = idx >> 7, nn = idx & 127;
        float conf = g_pool[(b * CMn + cc) * 16 + np];
        g_localh[((size_t)bn * 80 + cc) * 512 + nBase + nn] =
            __float2half(u.C[cc * 136 + nn] * conf);
    }
}

// ---------------- 4. k = local @ Wk + bk (WMMA, half out) ----------------
__global__ __launch_bounds__(320, 2) void k_kproj_w(const float* __restrict__ bk) {
    __shared__ __align__(16) union {
        struct { __half A[80][40]; __half B[32][136]; } ab;
        float C[80 * 136];
    } u;
    int bn = blockIdx.y;
    int nBase = blockIdx.x * 128;
    const __half* Ap = g_localh + (size_t)bn * 80 * 512;
    int tid = threadIdx.x;
    int wid = tid >> 5;
    int wm = wid % 5, wn = wid / 5;

    wmma::fragment<wmma::accumulator, 16, 16, 16, float> c[4];
#pragma unroll
    for (int j = 0; j < 4; j++) wmma::fill_fragment(c[j], 0.f);

    for (int k0 = 0; k0 < 512; k0 += 32) {
        {
            int cc = tid >> 2;
            int h8 = (tid & 3) * 8;
            *(uint4*)&u.ab.A[cc][h8] = *(const uint4*)&Ap[(size_t)cc * 512 + k0 + h8];
        }
        for (int idx = tid; idx < 512; idx += 320) {
            int kk = idx >> 4;
            int nn = (idx & 15) * 8;
            *(uint4*)&u.ab.B[kk][nn] = *(const uint4*)&g_Wk_h[(k0 + kk) * MID + nBase + nn];
        }
        __syncthreads();
#pragma unroll
        for (int ks = 0; ks < 32; ks += 16) {
            wmma::fragment<wmma::matrix_a, 16, 16, 16, __half, wmma::row_major> af;
            wmma::load_matrix_sync(af, &u.ab.A[wm * 16][ks], 40);
#pragma unroll
            for (int j = 0; j < 4; j++) {
                wmma::fragment<wmma::matrix_b, 16, 16, 16, __half, wmma::row_major> bf;
                wmma::load_matrix_sync(bf, &u.ab.B[ks][wn * 64 + j * 16], 136);
                wmma::mma_sync(c[j], af, bf, c[j]);
            }
        }
        __syncthreads();
    }
#pragma unroll
    for (int j = 0; j < 4; j++)
        wmma::store_matrix_sync(&u.C[(wm * 16) * 136 + wn * 64 + j * 16], c[j], 136,
                                wmma::mem_row_major);
    __syncthreads();
    for (int idx = tid; idx < 76 * 128; idx += 320) {
        int cc = idx >> 7, nn = idx & 127;
        g_kkh[((size_t)bn * 76 + cc) * 256 + nBase + nn] =
            __float2half(u.C[cc * 136 + nn] + bk[nBase + nn]);
    }
}

// ---------------- 5. v = g @ Wv + bv (half out) ----------------
__global__ void k_v(const float* __restrict__ g, const float* __restrict__ Wv,
                    const float* __restrict__ bv) {
    __shared__ float sg[512];
    int c = blockIdx.x, t = threadIdx.x;
    for (int k = t; k < 512; k += 256) sg[k] = g[c * 512 + k];
    __syncthreads();
    float acc = 0.f;
    for (int k = 0; k < 512; k++) acc += sg[k] * Wv[k * MID + t];
    g_vvh[c * MID + t] = __float2half(acc + bv[t]);
}

// ---------------- 6. q = x^T @ Wq + bq  (WMMA, half out, patch-major) ------
__device__ __forceinline__ void q_stage(int tid, __half* Adst, __half* Bdst,
                                        const __half* xb, int k0, int mBase, int nBase) {
#pragma unroll
    for (int l = 0; l < 4; l++) {
        int idx = tid + l * 256;
        if (idx < 512) {
            int kk = idx >> 4, m = (idx & 15) * 8;
            cp16(Adst + kk * 136 + m, xb + (size_t)(k0 + kk) * HW + mBase + m);
        } else {
            int j = idx - 512;
            int kk = j >> 4, n = (j & 15) * 8;
            cp16(Bdst + kk * 136 + n, g_Wq_h + (k0 + kk) * MID + nBase + n);
        }
    }
    cp_commit();
}

__global__ __launch_bounds__(256, 2) void k_q_w() {
    __shared__ __align__(16) union {
        struct { __half A[2][32][136]; __half B[2][32][136]; } s;
        float scr[8][16][20];
    } u;
    int b = blockIdx.z;
    int r = blockIdx.y;
    int mBase = r * 128;
    int nBase = blockIdx.x * 128;
    const __half* xb = g_xh + (size_t)b * Cc * HW;
    int tid = threadIdx.x;
    int lane = tid & 31;
    int wid = tid >> 5;
    int wm = wid & 3;
    int wn = wid >> 2;

    wmma::fragment<wmma::accumulator, 16, 16, 16, float> c[2][4];
#pragma unroll
    for (int i = 0; i < 2; i++)
#pragma unroll
        for (int j = 0; j < 4; j++)
            wmma::load_matrix_sync(c[i][j], g_qbias + nBase + wn * 64 + j * 16, MID,
                                   wmma::mem_row_major);

    q_stage(tid, &u.s.A[0][0][0], &u.s.B[0][0][0], xb, 0, mBase, nBase);
    for (int it = 0; it < 16; it++) {
        if (it + 1 < 16) {
            int s2 = (it + 1) & 1;
            q_stage(tid, &u.s.A[s2][0][0], &u.s.B[s2][0][0], xb, (it + 1) * 32, mBase, nBase);
            cp_wait<1>();
        } else {
            cp_wait<0>();
        }
        __syncthreads();
        int s = it & 1;
#pragma unroll
        for (int ks = 0; ks < 32; ks += 16) {
            wmma::fragment<wmma::matrix_a, 16, 16, 16, __half, wmma::col_major> af[2];
            wmma::fragment<wmma::matrix_b, 16, 16, 16, __half, wmma::row_major> bf[4];
#pragma unroll
            for (int i = 0; i < 2; i++)
                wmma::load_matrix_sync(af[i], &u.s.A[s][ks][wm * 32 + i * 16], 136);
#pragma unroll
            for (int j = 0; j < 4; j++)
                wmma::load_matrix_sync(bf[j], &u.s.B[s][ks][wn * 64 + j * 16], 136);
#pragma unroll
            for (int i = 0; i < 2; i++)
#pragma unroll
                for (int j = 0; j < 4; j++)
                    wmma::mma_sync(c[i][j], af[i], bf[j], c[i][j]);
        }
        __syncthreads();
    }
    // half store through per-warp scratch (ld=20, multiple of 4); patch-major layout
    int bn = b * 16 + (r >> 5) * 4 + wm;
    int prow = r & 31;
#pragma unroll
    for (int i = 0; i < 2; i++) {
        size_t rowbase = (size_t)bn * 1024 + prow * 32 + i * 16;
#pragma unroll
        for (int j = 0; j < 4; j++) {
            wmma::store_matrix_sync(&u.scr[wid][0][0], c[i][j], 20, wmma::mem_row_major);
            __syncwarp();
            scr_to_half(&u.scr[wid][0][0],
                        g_qh + rowbase * 256 + nBase + wn * 64 + j * 16, 256, lane);
            __syncwarp();
        }
    }
}

// ---------------- 7. attention (WMMA): S=QK^T, softmax, O=PV (half out) ----
__global__ __launch_bounds__(256, 2) void k_att_w() {
    __shared__ __align__(16) union {
        struct { __half Q[64][72]; __half K[80][72]; } a;
        __half P[64][88];
    } uA;
    __shared__ __align__(16) union {
        float S[64][92];
        __half V[80][136];
    } uB;
    __shared__ __align__(16) float scr[8][16][20];
    int bn = blockIdx.y;
    int mBase = blockIdx.x * 64;
    int tid = threadIdx.x;
    int lane = tid & 31;
    int wid = tid >> 5;
    int wm = wid & 3;
    int wn = wid >> 2;
    const __half* qsrc = g_qh + ((size_t)bn * 1024 + mBase) * 256;
    const __half* ksrc = g_kkh + (size_t)bn * 76 * 256;

    int nfr = (wn == 0) ? 3 : 2;
    int nb0 = (wn == 0) ? 0 : 48;
    wmma::fragment<wmma::accumulator, 16, 16, 16, float> sacc[3];
#pragma unroll
    for (int f = 0; f < 3; f++) wmma::fill_fragment(sacc[f], 0.f);

    for (int k0 = 0; k0 < 256; k0 += 64) {
        // stage Q (pure half copy)
        for (int idx = tid; idx < 512; idx += 256) {
            int row = idx >> 3, c8 = (idx & 7) * 8;
            *(uint4*)&uA.a.Q[row][c8] = *(const uint4*)&qsrc[(size_t)row * 256 + k0 + c8];
        }
        // stage K (80 rows, pad zero)
        for (int idx = tid; idx < 640; idx += 256) {
            int row = idx >> 3, c8 = (idx & 7) * 8;
            uint4 z = {0, 0, 0, 0};
            uint4 val = (row < 76) ? *(const uint4*)&ksrc[(size_t)row * 256 + k0 + c8] : z;
            *(uint4*)&uA.a.K[row][c8] = val;
        }
        __syncthreads();
#pragma unroll
        for (int ks = 0; ks < 64; ks += 16) {
            wmma::fragment<wmma::matrix_a, 16, 16, 16, __half, wmma::row_major> af;
            wmma::load_matrix_sync(af, &uA.a.Q[wm * 16][ks], 72);
            for (int f = 0; f < nfr; f++) {
                wmma::fragment<wmma::matrix_b, 16, 16, 16, __half, wmma::col_major> bf;
                wmma::load_matrix_sync(bf, &uA.a.K[nb0 + f * 16][ks], 72);
                wmma::mma_sync(sacc[f], af, bf, sacc[f]);
            }
        }
        __syncthreads();
    }
    for (int f = 0; f < nfr; f++)
        wmma::store_matrix_sync(&uB.S[wm * 16][nb0 + f * 16], sacc[f], 92,
                                wmma::mem_row_major);
    __syncthreads();

    if (tid < 64) {
        float mx = -1e30f;
        for (int c = 0; c < 76; c++) mx = fmaxf(mx, uB.S[tid][c]);
        float s = 0.f;
        for (int c = 0; c < 76; c++) {
            float e = expf(uB.S[tid][c] - mx);
            uB.S[tid][c] = e;
            s += e;
        }
        float inv = 1.0f / s;
        for (int c = 0; c < 76; c++) uA.P[tid][c] = __float2half(uB.S[tid][c] * inv);
        uA.P[tid][76] = __float2half(0.f);
        uA.P[tid][77] = __float2half(0.f);
        uA.P[tid][78] = __float2half(0.f);
        uA.P[tid][79] = __float2half(0.f);
    }
    __syncthreads();

    for (int hb = 0; hb < 2; hb++) {
        for (int idx = tid; idx < 1280; idx += 256) {
            int row = idx >> 4, c8 = (idx & 15) * 8;
            uint4 z = {0, 0, 0, 0};
            uint4 val = (row < 76) ? *(const uint4*)&g_vvh[row * 256 + hb * 128 + c8] : z;
            *(uint4*)&uB.V[row][c8] = val;
        }
        __syncthreads();
        wmma::fragment<wmma::accumulator, 16, 16, 16, float> oacc[4];
#pragma unroll
        for (int j = 0; j < 4; j++) wmma::fill_fragment(oacc[j], 0.f);
#pragma unroll
        for (int kc = 0; kc < 5; kc++) {
            int ks = kc * 16;
            wmma::fragment<wmma::matrix_a, 16, 16, 16, __half, wmma::row_major> pf;
            wmma::load_matrix_sync(pf, &uA.P[wm * 16][ks], 88);
#pragma unroll
            for (int j = 0; j < 4; j++) {
                wmma::fragment<wmma::matrix_b, 16, 16, 16, __half, wmma::row_major> vf;
                wmma::load_matrix_sync(vf, &uB.V[ks][wn * 64 + j * 16], 136);
                wmma::mma_sync(oacc[j], pf, vf, oacc[j]);
            }
        }
        __half* obase = g_oh + ((size_t)bn * 1024 + mBase + wm * 16) * 256 + hb * 128 + wn * 64;
#pragma unroll
        for (int j = 0; j < 4; j++) {
            wmma::store_matrix_sync(&scr[wid][0][0], oacc[j], 20, wmma::mem_row_major);
            __syncwarp();
            scr_to_half(&scr[wid][0][0], obase + j * 16, 256, lane);
            __syncwarp();
        }
        __syncthreads();
    }
}

// ---------------- 8. conv (WMMA) + BN + ReLU, patch-major A ----------------
__global__ __launch_bounds__(256, 2) void k_conv_w(const float* __restrict__ gamma,
                                                   const float* __restrict__ beta,
                                                   const float* __restrict__ mean,
                                                   const float* __restrict__ var,
                                                   float* __restrict__ y) {
    __shared__ __align__(16) union {
        struct { __half A[128][40]; __half B[32][72]; } ab;
        float C[64 * 136];
    } u;
    int nBase = blockIdx.x * 64;
    int mBase = blockIdx.y * 128;
    int tid = threadIdx.x;
    int wid = tid >> 5;
    int wm = wid & 3;
    int wn = wid >> 2;

    wmma::fragment<wmma::accumulator, 16, 16, 16, float> c[2][2];
#pragma unroll
    for (int i = 0; i < 2; i++)
#pragma unroll
        for (int j = 0; j < 2; j++) wmma::fill_fragment(c[i][j], 0.f);

    for (int k0 = 0; k0 < 256; k0 += 32) {
        // A: 128 x 32 halves (512 uint4) — pure copy
#pragma unroll
        for (int l = 0; l < 2; l++) {
            int idx = tid + l * 256;
            int m = idx >> 2;
            int k8 = (idx & 3) * 8;
            *(uint4*)&u.ab.A[m][k8] = *(const uint4*)&g_oh[(size_t)(mBase + m) * 256 + k0 + k8];
        }
        {
            int kk = tid >> 3;
            int n = (tid & 7) * 8;
            *(uint4*)&u.ab.B[kk][n] = *(const uint4*)&g_Wc_h[(k0 + kk) * Cc + nBase + n];
        }
        __syncthreads();
#pragma unroll
        for (int ks = 0; ks < 32; ks += 16) {
            wmma::fragment<wmma::matrix_a, 16, 16, 16, __half, wmma::row_major> af[2];
            wmma::fragment<wmma::matrix_b, 16, 16, 16, __half, wmma::row_major> bf[2];
#pragma unroll
            for (int i = 0; i < 2; i++)
                wmma::load_matrix_sync(af[i], &u.ab.A[wm * 32 + i * 16][ks], 40);
#pragma unroll
            for (int j = 0; j < 2; j++)
                wmma::load_matrix_sync(bf[j], &u.ab.B[ks][wn * 32 + j * 16], 72);
#pragma unroll
            for (int i = 0; i < 2; i++)
#pragma unroll
                for (int j = 0; j < 2; j++)
                    wmma::mma_sync(c[i][j], af[i], bf[j], c[i][j]);
        }
        __syncthreads();
    }

#pragma unroll
    for (int i = 0; i < 2; i++)
#pragma unroll
        for (int j = 0; j < 2; j++)
            wmma::store_matrix_sync(&u.C[(wn * 32 + j * 16) * 136 + wm * 32 + i * 16],
                                    c[i][j], 136, wmma::mem_col_major);
    __syncthreads();

    {
        int n = tid >> 2;
        int q4 = tid & 3;
        int ch = nBase + n;
        float iv = gamma[ch] / sqrtf(var[ch] + 1e-5f);
        float ad = beta[ch] - mean[ch] * iv;
        int bn = mBase >> 10;
        int pp0 = mBase & 1023;
        int b = bn >> 4, np = bn & 15;
        int i0 = (np >> 2) * 32, j0 = (np & 3) * 32;
        float* ybase = y + ((size_t)b * Cc + ch) * HW;
        const float* crow = &u.C[n * 136];
#pragma unroll
        for (int l = 0; l < 8; l++) {
            int m = (q4 + l * 4) * 4;
            int p = pp0 + m;
            float4 v = *(const float4*)&crow[m];
            v.x = fmaxf(v.x * iv + ad, 0.f);
            v.y = fmaxf(v.y * iv + ad, 0.f);
            v.z = fmaxf(v.z * iv + ad, 0.f);
            v.w = fmaxf(v.w * iv + ad, 0.f);
            *(float4*)&ybase[(i0 + (p >> 5)) * 128 + j0 + (p & 31)] = v;
        }
    }
}

// ---------------- launcher ----------------
extern "C" void kernel_launch(void* const* d_in, const int* in_sizes, int n_in,
                              void* d_out, int out_size) {
    const float* x   = (const float*)d_in[0];
    const float* sim = (const float*)d_in[1];
    const float* gcc = (const float*)d_in[2];
    const float* Wq  = (const float*)d_in[3];
    const float* bq  = (const float*)d_in[4];
    const float* Wk  = (const float*)d_in[5];
    const float* bk  = (const float*)d_in[6];
    const float* Wv  = (const float*)d_in[7];
    const float* bv  = (const float*)d_in[8];
    const float* Wc  = (const float*)d_in[9];
    const float* gm  = (const float*)d_in[10];
    const float* bt  = (const float*)d_in[11];
    const float* mn  = (const float*)d_in[12];
    const float* vr  = (const float*)d_in[13];
    float* y = (float*)d_out;
    float* tail = y + (size_t)Bsz * Cc * HW;

    k_setup<<<256, 256>>>(Wq, Wk, Wc, bq);
    k_xh<<<8192, 256>>>(x);
    k_poolsm<<<Bsz * Np * CMn, 256>>>(sim, tail);
    k_local_w<<<dim3(4, 64), 320>>>();
    k_kproj_w<<<dim3(2, 64), 320>>>(bk);
    k_v<<<CMn, 256>>>(gcc, Wv, bv);
    k_q_w<<<dim3(2, 128, 4), 256>>>();
    k_att_w<<<dim3(16, 64), 256>>>();
    k_conv_w<<<dim3(8, 512), 256>>>(gm, bt, mn, vr, y);
}

// round 11
// speedup vs baseline: 6.0603x; 1.0216x over previous
#include <cuda_runtime.h>
#include <cuda_fp16.h>
#include <mma.h>
#include <math.h>

using namespace nvcuda;

#define Bsz 4
#define Cc 512
#define MID 256
#define CMn 76
#define Hh 128
#define Ww 128
#define HW 16384
#define Pp 1024
#define Np 16

// ---------------- static scratch ----------------
__device__ float  g_pool[Bsz * CMn * Np];
__device__ __half g_smxh[(size_t)64 * 80 * 1024];       // softmax(sim), padded 80 rows
__device__ __half g_localh[(size_t)64 * 80 * 512];      // local (conf folded), padded
__device__ __half g_kkh[(size_t)64 * 76 * 256];         // k proj (half)
__device__ __half g_vvh[76 * 256];                      // v proj (half)
__device__ __half g_oh[(size_t)64 * 1024 * 256];        // attn out HALF, patch-major
__device__ __half g_xh[(size_t)Bsz * Cc * HW];          // x as half
__device__ __half g_Wq_h[Cc * MID];
__device__ __half g_Wk_h[Cc * MID];
__device__ __half g_Wc_h[MID * Cc];
__device__ float  g_qbias[16 * MID];

// ---------------- cp.async helpers ----------------
__device__ __forceinline__ void cp16(void* dst, const void* src) {
    unsigned d = (unsigned)__cvta_generic_to_shared(dst);
    asm volatile("cp.async.ca.shared.global [%0], [%1], 16;\n" :: "r"(d), "l"(src));
}
__device__ __forceinline__ void cp_commit() { asm volatile("cp.async.commit_group;\n"); }
template <int N>
__device__ __forceinline__ void cp_wait() { asm volatile("cp.async.wait_group %0;\n" :: "n"(N)); }

// convert a 16x16 fp32 warp scratch tile (ld=20) to half and write out (ldg mult of 8).
// caller must __syncwarp() between the scratch store and this call.
__device__ __forceinline__ void scr_to_half(const float* scr, __half* gdst, int ldg, int lane) {
    int rr = lane >> 1, c8 = (lane & 1) * 8;
    const float* s = scr + rr * 20 + c8;
    __half2 h0 = __floats2half2_rn(s[0], s[1]);
    __half2 h1 = __floats2half2_rn(s[2], s[3]);
    __half2 h2 = __floats2half2_rn(s[4], s[5]);
    __half2 h3 = __floats2half2_rn(s[6], s[7]);
    uint4 o;
    o.x = *(unsigned*)&h0; o.y = *(unsigned*)&h1;
    o.z = *(unsigned*)&h2; o.w = *(unsigned*)&h3;
    *(uint4*)(gdst + (size_t)rr * ldg + c8) = o;
}

// ---------------- 0. merged misc: setup + x->half + pool/softmax + v -------
// grid: [0,256) setup | [256,2304) xh | [2304,7168) poolsm | [7168,7244) v
__global__ void k_misc(const float* __restrict__ x, const float* __restrict__ sim,
                       const float* __restrict__ gcc,
                       const float* __restrict__ Wq, const float* __restrict__ Wk,
                       const float* __restrict__ Wc, const float* __restrict__ bq,
                       const float* __restrict__ Wv, const float* __restrict__ bv,
                       float* __restrict__ out_tail) {
    __shared__ float red[256];
    __shared__ float sg[512];
    int blk = blockIdx.x;
    int t = threadIdx.x;

    if (blk < 256) {
        // ---- setup: weight conversions, bias tile, zero pads ----
        int g = blk * 256 + t;
        int stride = 256 * 256;
        for (int i = g; i < Cc * MID; i += stride) {
            g_Wq_h[i] = __float2half(Wq[i]);
            g_Wk_h[i] = __float2half(Wk[i]);
            g_Wc_h[i] = __float2half(Wc[i]);
        }
        for (int i = g; i < 16 * MID; i += stride) g_qbias[i] = bq[i & (MID - 1)];
        for (int i = g; i < 64 * 4 * 1024; i += stride) {
            int bn = i >> 12, rem = i & 4095;
            g_smxh[((size_t)bn * 80 + 76) * 1024 + rem] = __float2half(0.f);
        }
        for (int i = g; i < 64 * 4 * 512; i += stride) {
            int bn = i >> 11, rem = i & 2047;
            g_localh[((size_t)bn * 80 + 76) * 512 + rem] = __float2half(0.f);
        }
    } else if (blk < 2304) {
        // ---- x -> half ----
        size_t n8 = (size_t)Bsz * Cc * HW / 8;
        size_t g = (size_t)(blk - 256) * 256 + t;
        size_t stride = (size_t)2048 * 256;
        for (; g < n8; g += stride) {
            const float4* s = (const float4*)x + g * 2;
            float4 a = s[0], b = s[1];
            __half2 h0 = __floats2half2_rn(a.x, a.y);
            __half2 h1 = __floats2half2_rn(a.z, a.w);
            __half2 h2 = __floats2half2_rn(b.x, b.y);
            __half2 h3 = __floats2half2_rn(b.z, b.w);
            uint4 o;
            o.x = *(unsigned*)&h0; o.y = *(unsigned*)&h1;
            o.z = *(unsigned*)&h2; o.w = *(unsigned*)&h3;
            ((uint4*)g_xh)[g] = o;
        }
    } else if (blk < 7168) {
        // ---- fused pool + softmax ----
        int id = blk - 2304;
        int cm = id % CMn;
        int bn = id / CMn;
        int n = bn & 15, b = bn >> 4;
        int i0 = (n >> 2) * 32, j0 = (n & 3) * 32;
        const float* base = sim + ((size_t)b * CMn + cm) * HW;
        float v[4];
        float mx = -1e30f, sraw = 0.f;
#pragma unroll
        for (int it = 0; it < 4; it++) {
            int p = t + it * 256;
            int pi = p >> 5, pj = p & 31;
            v[it] = base[(i0 + pi) * Ww + j0 + pj];
            mx = fmaxf(mx, v[it]);
            sraw += v[it];
        }
        red[t] = sraw; __syncthreads();
        for (int o = 128; o > 0; o >>= 1) {
            if (t < o) red[t] += red[t + o];
            __syncthreads();
        }
        if (t == 0) {
            float m = red[0] * (1.0f / 1024.0f);
            int pid = (b * CMn + cm) * 16 + n;
            g_pool[pid] = m;
            out_tail[pid] = m;
        }
        __syncthreads();
        red[t] = mx; __syncthreads();
        for (int o = 128; o > 0; o >>= 1) {
            if (t < o) red[t] = fmaxf(red[t], red[t + o]);
            __syncthreads();
        }
        float gmx = red[0]; __syncthreads();
        float s = 0.f;
#pragma unroll
        for (int it = 0; it < 4; it++) { v[it] = expf(v[it] - gmx); s += v[it]; }
        red[t] = s; __syncthreads();
        for (int o = 128; o > 0; o >>= 1) {
            if (t < o) red[t] += red[t + o];
            __syncthreads();
        }
        float inv = 1.0f / red[0];
        __half* dst = g_smxh + ((size_t)bn * 80 + cm) * Pp;
#pragma unroll
        for (int it = 0; it < 4; it++) { int p = t + it * 256; dst[p] = __float2half(v[it] * inv); }
    } else {
        // ---- v = g @ Wv + bv ----
        int c = blk - 7168;
        for (int k = t; k < 512; k += 256) sg[k] = gcc[c * 512 + k];
        __syncthreads();
        float acc = 0.f;
        for (int k = 0; k < 512; k++) acc += sg[k] * Wv[k * MID + t];
        g_vvh[c * MID + t] = __float2half(acc + bv[t]);
    }
}

// ---------------- 3. local = smx^T @ xs * conf  (WMMA, cp.async x2) --------
__device__ __forceinline__ void local_stage(int tid, __half* Adst, __half* Bdst,
                                            const __half* Asrc, const __half* Bsrc,
                                            int it, int nBase, int baseoff) {
    for (int idx = tid; idx < 832; idx += 320) {
        if (idx < 320) {
            int row = idx >> 2, col = (idx & 3) * 8;
            cp16(Adst + row * 40 + col, Asrc + (size_t)row * 1024 + it * 32 + col);
        } else {
            int j = idx - 320;
            int row = j >> 2, col = (j & 3) * 8;
            cp16(Bdst + row * 40 + col,
                 Bsrc + (size_t)(nBase + row) * HW + baseoff + it * Ww + col);
        }
    }
    cp_commit();
}

__global__ __launch_bounds__(320, 2) void k_local_w() {
    __shared__ __align__(16) union {
        struct { __half A[2][80][40]; __half B[2][128][40]; } s;
        float C[80 * 136];
    } u;
    int bn = blockIdx.y;
    int b = bn >> 4, np = bn & 15;
    int i0 = (np >> 2) * 32, j0 = (np & 3) * 32;
    int baseoff = i0 * Ww + j0;
    int nBase = blockIdx.x * 128;
    const __half* Asrc = g_smxh + (size_t)bn * 80 * 1024;
    const __half* Bsrc = g_xh + (size_t)b * Cc * HW;
    int tid = threadIdx.x;
    int wid = tid >> 5;
    int wm = wid % 5, wn = wid / 5;

    wmma::fragment<wmma::accumulator, 16, 16, 16, float> c[4];
#pragma unroll
    for (int j = 0; j < 4; j++) wmma::fill_fragment(c[j], 0.f);

    local_stage(tid, &u.s.A[0][0][0], &u.s.B[0][0][0], Asrc, Bsrc, 0, nBase, baseoff);
    for (int it = 0; it < 32; it++) {
        if (it + 1 < 32) {
            int s2 = (it + 1) & 1;
            local_stage(tid, &u.s.A[s2][0][0], &u.s.B[s2][0][0], Asrc, Bsrc, it + 1, nBase, baseoff);
            cp_wait<1>();
        } else {
            cp_wait<0>();
        }
        __syncthreads();
        int s = it & 1;
#pragma unroll
        for (int ks = 0; ks < 32; ks += 16) {
            wmma::fragment<wmma::matrix_a, 16, 16, 16, __half, wmma::row_major> af;
            wmma::load_matrix_sync(af, &u.s.A[s][wm * 16][ks], 40);
#pragma unroll
            for (int j = 0; j < 4; j++) {
                wmma::fragment<wmma::matrix_b, 16, 16, 16, __half, wmma::col_major> bf;
                wmma::load_matrix_sync(bf, &u.s.B[s][wn * 64 + j * 16][ks], 40);
                wmma::mma_sync(c[j], af, bf, c[j]);
            }
        }
        __syncthreads();
    }
#pragma unroll
    for (int j = 0; j < 4; j++)
        wmma::store_matrix_sync(&u.C[(wm * 16) * 136 + wn * 64 + j * 16], c[j], 136,
                                wmma::mem_row_major);
    __syncthreads();
    for (int idx = tid; idx < 76 * 128; idx += 320) {
        int cc = idx >> 7, nn = idx & 127;
        float conf = g_pool[(b * CMn + cc) * 16 + np];
        g_localh[((size_t)bn * 80 + cc) * 512 + nBase + nn] =
            __float2half(u.C[cc * 136 + nn] * conf);
    }
}

// ---------------- 4. k = local @ Wk + bk (WMMA, half out) ----------------
__global__ __launch_bounds__(320, 2) void k_kproj_w(const float* __restrict__ bk) {
    __shared__ __align__(16) union {
        struct { __half A[80][40]; __half B[32][136]; } ab;
        float C[80 * 136];
    } u;
    int bn = blockIdx.y;
    int nBase = blockIdx.x * 128;
    const __half* Ap = g_localh + (size_t)bn * 80 * 512;
    int tid = threadIdx.x;
    int wid = tid >> 5;
    int wm = wid % 5, wn = wid / 5;

    wmma::fragment<wmma::accumulator, 16, 16, 16, float> c[4];
#pragma unroll
    for (int j = 0; j < 4; j++) wmma::fill_fragment(c[j], 0.f);

    for (int k0 = 0; k0 < 512; k0 += 32) {
        {
            int cc = tid >> 2;
            int h8 = (tid & 3) * 8;
            *(uint4*)&u.ab.A[cc][h8] = *(const uint4*)&Ap[(size_t)cc * 512 + k0 + h8];
        }
        for (int idx = tid; idx < 512; idx += 320) {
            int kk = idx >> 4;
            int nn = (idx & 15) * 8;
            *(uint4*)&u.ab.B[kk][nn] = *(const uint4*)&g_Wk_h[(k0 + kk) * MID + nBase + nn];
        }
        __syncthreads();
#pragma unroll
        for (int ks = 0; ks < 32; ks += 16) {
            wmma::fragment<wmma::matrix_a, 16, 16, 16, __half, wmma::row_major> af;
            wmma::load_matrix_sync(af, &u.ab.A[wm * 16][ks], 40);
#pragma unroll
            for (int j = 0; j < 4; j++) {
                wmma::fragment<wmma::matrix_b, 16, 16, 16, __half, wmma::row_major> bf;
                wmma::load_matrix_sync(bf, &u.ab.B[ks][wn * 64 + j * 16], 136);
                wmma::mma_sync(c[j], af, bf, c[j]);
            }
        }
        __syncthreads();
    }
#pragma unroll
    for (int j = 0; j < 4; j++)
        wmma::store_matrix_sync(&u.C[(wm * 16) * 136 + wn * 64 + j * 16], c[j], 136,
                                wmma::mem_row_major);
    __syncthreads();
    for (int idx = tid; idx < 76 * 128; idx += 320) {
        int cc = idx >> 7, nn = idx & 127;
        g_kkh[((size_t)bn * 76 + cc) * 256 + nBase + nn] =
            __float2half(u.C[cc * 136 + nn] + bk[nBase + nn]);
    }
}

// ---------------- 7. fused q-proj + attention (dynamic smem) ----------------
// grid (16 mtiles, 64 bn), 256 threads (8 warps).
// Dynamic smem layout (bytes from base):
//   [0, 33792)        Qh half [64][264]        (later: P half [64][88] at 0)
//   [33792, 76800)    staging dbuf 2 x { As half[32][72] (4608) + Bs half[32][264] (16896) }
//   phase-S reuse:    K half[80][72] at 33792 (11520); S float[64][92] at 45312 (23552)
//   phase-Q epilogue: scr float[8][16][20] at 33792 (10240)
//   phase-PV:         V half[80][136] at 33792 (21760); scr at 55552 (10240)
#define ATTQ_SMEM 76800

__global__ __launch_bounds__(256) void k_attq() {
    extern __shared__ __align__(16) char dyn[];
    __half* Qh = (__half*)dyn;                         // ld 264
    int bn = blockIdx.y;
    int b = bn >> 4, np = bn & 15;
    int i0 = (np >> 2) * 32, j0 = (np & 3) * 32;
    int mBase = blockIdx.x * 64;
    int tid = threadIdx.x;
    int lane = tid & 31;
    int wid = tid >> 5;
    int wm = wid & 3;          // 4 warps over 64 px (16 each)
    int wn = wid >> 2;         // 2 warps over 256 mid (128 each)
    const __half* xb = g_xh + (size_t)b * Cc * HW;

    // ===== phase Q: Q[64][256] = x^T @ Wq + bq =====
    {
        wmma::fragment<wmma::accumulator, 16, 16, 16, float> c[8];
#pragma unroll
        for (int j = 0; j < 8; j++)
            wmma::load_matrix_sync(c[j], g_qbias + wn * 128 + j * 16, MID,
                                   wmma::mem_row_major);

        // stage helper inlined: 1280 cp16 per k0 (256 A + 1024 B), 5 per thread
        auto stage = [&](int s, int k0) {
#pragma unroll
            for (int l = 0; l < 5; l++) {
                int idx = tid + l * 256;
                char* base = dyn + 33792 + s * 21504;
                if (idx < 256) {
                    int ch = idx >> 3;
                    int px = (idx & 7) * 8;
                    int p = mBase + px;
                    cp16((__half*)base + ch * 72 + px,
                         xb + (size_t)(k0 + ch) * HW + (i0 + (p >> 5)) * 128 + j0 + (p & 31));
                } else {
                    int j = idx - 256;
                    int kk = j >> 5;
                    int n = (j & 31) * 8;
                    cp16((__half*)(base + 4608) + kk * 264 + n,
                         g_Wq_h + (k0 + kk) * MID + n);
                }
            }
            cp_commit();
        };

        stage(0, 0);
        for (int it = 0; it < 16; it++) {
            if (it + 1 < 16) {
                stage((it + 1) & 1, (it + 1) * 32);
                cp_wait<1>();
            } else {
                cp_wait<0>();
            }
            __syncthreads();
            int s = it & 1;
            __half* As = (__half*)(dyn + 33792 + s * 21504);
            __half* Bs = (__half*)(dyn + 33792 + s * 21504 + 4608);
#pragma unroll
            for (int ks = 0; ks < 32; ks += 16) {
                wmma::fragment<wmma::matrix_a, 16, 16, 16, __half, wmma::col_major> af;
                wmma::load_matrix_sync(af, As + ks * 72 + wm * 16, 72);
#pragma unroll
                for (int j = 0; j < 8; j++) {
                    wmma::fragment<wmma::matrix_b, 16, 16, 16, __half, wmma::row_major> bf;
                    wmma::load_matrix_sync(bf, Bs + ks * 264 + wn * 128 + j * 16, 264);
                    wmma::mma_sync(c[j], af, bf, c[j]);
                }
            }
            __syncthreads();
        }
        // write Q (half) into Qh via per-warp scratch
        float* scr = (float*)(dyn + 33792) + wid * 320;   // [16][20]
#pragma unroll
        for (int j = 0; j < 8; j++) {
            wmma::store_matrix_sync(scr, c[j], 20, wmma::mem_row_major);
            __syncwarp();
            scr_to_half(scr, Qh + (wm * 16) * 264 + wn * 128 + j * 16, 264, lane);
            __syncwarp();
        }
    }
    __syncthreads();

    // ===== phase S: S = Q @ K^T =====
    __half* Ksm = (__half*)(dyn + 33792);                // [80][72]
    float*  Sf  = (float*)(dyn + 45312);                 // [64][92]
    const __half* ksrc = g_kkh + (size_t)bn * 76 * 256;
    int nfr = (wn == 0) ? 3 : 2;
    int nb0 = (wn == 0) ? 0 : 48;
    {
        wmma::fragment<wmma::accumulator, 16, 16, 16, float> sacc[3];
#pragma unroll
        for (int f = 0; f < 3; f++) wmma::fill_fragment(sacc[f], 0.f);

        for (int k0 = 0; k0 < 256; k0 += 64) {
            for (int idx = tid; idx < 640; idx += 256) {
                int row = idx >> 3, c8 = (idx & 7) * 8;
                uint4 z = {0, 0, 0, 0};
                uint4 val = (row < 76) ? *(const uint4*)&ksrc[(size_t)row * 256 + k0 + c8] : z;
                *(uint4*)(Ksm + row * 72 + c8) = val;
            }
            __syncthreads();
#pragma unroll
            for (int ks = 0; ks < 64; ks += 16) {
                wmma::fragment<wmma::matrix_a, 16, 16, 16, __half, wmma::row_major> af;
                wmma::load_matrix_sync(af, Qh + (wm * 16) * 264 + k0 + ks, 264);
                for (int f = 0; f < nfr; f++) {
                    wmma::fragment<wmma::matrix_b, 16, 16, 16, __half, wmma::col_major> bf;
                    wmma::load_matrix_sync(bf, Ksm + (nb0 + f * 16) * 72 + ks, 72);
                    wmma::mma_sync(sacc[f], af, bf, sacc[f]);
                }
            }
            __syncthreads();
        }
        for (int f = 0; f < nfr; f++)
            wmma::store_matrix_sync(Sf + (wm * 16) * 92 + nb0 + f * 16, sacc[f], 92,
                                    wmma::mem_row_major);
    }
    __syncthreads();

    // ===== softmax -> P (half, overlays Qh region) =====
    __half* P = (__half*)dyn;                            // [64][88]
    if (tid < 64) {
        const float* srow = Sf + tid * 92;
        float mx = -1e30f;
        for (int c = 0; c < 76; c++) mx = fmaxf(mx, srow[c]);
        float s = 0.f;
        float e[76];
        for (int c = 0; c < 76; c++) { e[c] = expf(srow[c] - mx); s += e[c]; }
        float inv = 1.0f / s;
        __half* prow = P + tid * 88;
        for (int c = 0; c < 76; c++) prow[c] = __float2half(e[c] * inv);
        prow[76] = __float2half(0.f);
        prow[77] = __float2half(0.f);
        prow[78] = __float2half(0.f);
        prow[79] = __float2half(0.f);
    }
    __syncthreads();

    // ===== phase PV: O = P @ V =====
    __half* Vsm = (__half*)(dyn + 33792);                // [80][136]
    float* scr2 = (float*)(dyn + 55552) + wid * 320;     // [16][20] per warp
    for (int hb = 0; hb < 2; hb++) {
        for (int idx = tid; idx < 1280; idx += 256) {
            int row = idx >> 4, c8 = (idx & 15) * 8;
            uint4 z = {0, 0, 0, 0};
            uint4 val = (row < 76) ? *(const uint4*)&g_vvh[row * 256 + hb * 128 + c8] : z;
            *(uint4*)(Vsm + row * 136 + c8) = val;
        }
        __syncthreads();
        wmma::fragment<wmma::accumulator, 16, 16, 16, float> oacc[4];
#pragma unroll
        for (int j = 0; j < 4; j++) wmma::fill_fragment(oacc[j], 0.f);
#pragma unroll
        for (int kc = 0; kc < 5; kc++) {
            int ks = kc * 16;
            wmma::fragment<wmma::matrix_a, 16, 16, 16, __half, wmma::row_major> pf;
            wmma::load_matrix_sync(pf, P + (wm * 16) * 88 + ks, 88);
#pragma unroll
            for (int j = 0; j < 4; j++) {
                wmma::fragment<wmma::matrix_b, 16, 16, 16, __half, wmma::row_major> vf;
                wmma::load_matrix_sync(vf, Vsm + ks * 136 + wn * 64 + j * 16, 136);
                wmma::mma_sync(oacc[j], pf, vf, oacc[j]);
            }
        }
        __half* obase = g_oh + ((size_t)bn * 1024 + mBase + wm * 16) * 256 + hb * 128 + wn * 64;
#pragma unroll
        for (int j = 0; j < 4; j++) {
            wmma::store_matrix_sync(scr2, oacc[j], 20, wmma::mem_row_major);
            __syncwarp();
            scr_to_half(scr2, obase + j * 16, 256, lane);
            __syncwarp();
        }
        __syncthreads();
    }
}

// ---------------- 8. conv (WMMA) + BN + ReLU, patch-major A ----------------
__global__ __launch_bounds__(256, 2) void k_conv_w(const float* __restrict__ gamma,
                                                   const float* __restrict__ beta,
                                                   const float* __restrict__ mean,
                                                   const float* __restrict__ var,
                                                   float* __restrict__ y) {
    __shared__ __align__(16) union {
        struct { __half A[128][40]; __half B[32][72]; } ab;
        float C[64 * 136];
    } u;
    int nBase = blockIdx.x * 64;
    int mBase = blockIdx.y * 128;
    int tid = threadIdx.x;
    int wid = tid >> 5;
    int wm = wid & 3;
    int wn = wid >> 2;

    wmma::fragment<wmma::accumulator, 16, 16, 16, float> c[2][2];
#pragma unroll
    for (int i = 0; i < 2; i++)
#pragma unroll
        for (int j = 0; j < 2; j++) wmma::fill_fragment(c[i][j], 0.f);

    for (int k0 = 0; k0 < 256; k0 += 32) {
#pragma unroll
        for (int l = 0; l < 2; l++) {
            int idx = tid + l * 256;
            int m = idx >> 2;
            int k8 = (idx & 3) * 8;
            *(uint4*)&u.ab.A[m][k8] = *(const uint4*)&g_oh[(size_t)(mBase + m) * 256 + k0 + k8];
        }
        {
            int kk = tid >> 3;
            int n = (tid & 7) * 8;
            *(uint4*)&u.ab.B[kk][n] = *(const uint4*)&g_Wc_h[(k0 + kk) * Cc + nBase + n];
        }
        __syncthreads();
#pragma unroll
        for (int ks = 0; ks < 32; ks += 16) {
            wmma::fragment<wmma::matrix_a, 16, 16, 16, __half, wmma::row_major> af[2];
            wmma::fragment<wmma::matrix_b, 16, 16, 16, __half, wmma::row_major> bf[2];
#pragma unroll
            for (int i = 0; i < 2; i++)
                wmma::load_matrix_sync(af[i], &u.ab.A[wm * 32 + i * 16][ks], 40);
#pragma unroll
            for (int j = 0; j < 2; j++)
                wmma::load_matrix_sync(bf[j], &u.ab.B[ks][wn * 32 + j * 16], 72);
#pragma unroll
            for (int i = 0; i < 2; i++)
#pragma unroll
                for (int j = 0; j < 2; j++)
                    wmma::mma_sync(c[i][j], af[i], bf[j], c[i][j]);
        }
        __syncthreads();
    }

#pragma unroll
    for (int i = 0; i < 2; i++)
#pragma unroll
        for (int j = 0; j < 2; j++)
            wmma::store_matrix_sync(&u.C[(wn * 32 + j * 16) * 136 + wm * 32 + i * 16],
                                    c[i][j], 136, wmma::mem_col_major);
    __syncthreads();

    {
        int n = tid >> 2;
        int q4 = tid & 3;
        int ch = nBase + n;
        float iv = gamma[ch] / sqrtf(var[ch] + 1e-5f);
        float ad = beta[ch] - mean[ch] * iv;
        int bn = mBase >> 10;
        int pp0 = mBase & 1023;
        int b = bn >> 4, np = bn & 15;
        int i0 = (np >> 2) * 32, j0 = (np & 3) * 32;
        float* ybase = y + ((size_t)b * Cc + ch) * HW;
        const float* crow = &u.C[n * 136];
#pragma unroll
        for (int l = 0; l < 8; l++) {
            int m = (q4 + l * 4) * 4;
            int p = pp0 + m;
            float4 v = *(const float4*)&crow[m];
            v.x = fmaxf(v.x * iv + ad, 0.f);
            v.y = fmaxf(v.y * iv + ad, 0.f);
            v.z = fmaxf(v.z * iv + ad, 0.f);
            v.w = fmaxf(v.w * iv + ad, 0.f);
            *(float4*)&ybase[(i0 + (p >> 5)) * 128 + j0 + (p & 31)] = v;
        }
    }
}

// ---------------- launcher ----------------
extern "C" void kernel_launch(void* const* d_in, const int* in_sizes, int n_in,
                              void* d_out, int out_size) {
    const float* x   = (const float*)d_in[0];
    const float* sim = (const float*)d_in[1];
    const float* gcc = (const float*)d_in[2];
    const float* Wq  = (const float*)d_in[3];
    const float* bq  = (const float*)d_in[4];
    const float* Wk  = (const float*)d_in[5];
    const float* bk  = (const float*)d_in[6];
    const float* Wv  = (const float*)d_in[7];
    const float* bv  = (const float*)d_in[8];
    const float* Wc  = (const float*)d_in[9];
    const float* gm  = (const float*)d_in[10];
    const float* bt  = (const float*)d_in[11];
    const float* mn  = (const float*)d_in[12];
    const float* vr  = (const float*)d_in[13];
    float* y = (float*)d_out;
    float* tail = y + (size_t)Bsz * Cc * HW;

    cudaFuncSetAttribute(k_attq, cudaFuncAttributeMaxDynamicSharedMemorySize, ATTQ_SMEM);

    k_misc<<<7244, 256>>>(x, sim, gcc, Wq, Wk, Wc, bq, Wv, bv, tail);
    k_local_w<<<dim3(4, 64), 320>>>();
    k_kproj_w<<<dim3(2, 64), 320>>>(bk);
    k_attq<<<dim3(16, 64), 256, ATTQ_SMEM>>>();
    k_conv_w<<<dim3(8, 512), 256>>>(gm, bt, mn, vr, y);
}

// round 12
// speedup vs baseline: 6.3533x; 1.0483x over previous
#include <cuda_runtime.h>
#include <cuda_fp16.h>
#include <mma.h>
#include <math.h>

using namespace nvcuda;

#define Bsz 4
#define Cc 512
#define MID 256
#define CMn 76
#define Hh 128
#define Ww 128
#define HW 16384
#define Pp 1024
#define Np 16

// ---------------- static scratch ----------------
__device__ float  g_pool[Bsz * CMn * Np];
__device__ __half g_smxh[(size_t)64 * 80 * 1024];       // softmax(sim), padded 80 rows
__device__ __half g_localh[(size_t)64 * 80 * 512];      // local (conf folded), padded
__device__ __half g_kkh[(size_t)64 * 76 * 256];         // k proj (half)
__device__ __half g_vvh[76 * 256];                      // v proj (half)
__device__ __half g_oh[(size_t)64 * 1024 * 256];        // attn out HALF, patch-major
__device__ __half g_xh[(size_t)Bsz * Cc * HW];          // x as half
__device__ __half g_Wq_h[Cc * MID];
__device__ __half g_Wk_h[Cc * MID];
__device__ __half g_Wc_h[MID * Cc];
__device__ float  g_qbias[16 * MID];

// ---------------- cp.async helpers ----------------
__device__ __forceinline__ void cp16(void* dst, const void* src) {
    unsigned d = (unsigned)__cvta_generic_to_shared(dst);
    asm volatile("cp.async.ca.shared.global [%0], [%1], 16;\n" :: "r"(d), "l"(src));
}
__device__ __forceinline__ void cp_commit() { asm volatile("cp.async.commit_group;\n"); }
template <int N>
__device__ __forceinline__ void cp_wait() { asm volatile("cp.async.wait_group %0;\n" :: "n"(N)); }

// convert a 16x16 fp32 warp scratch tile (ld=20) to half and write out (ldg mult of 8).
// caller must __syncwarp() between the scratch store and this call.
__device__ __forceinline__ void scr_to_half(const float* scr, __half* gdst, int ldg, int lane) {
    int rr = lane >> 1, c8 = (lane & 1) * 8;
    const float* s = scr + rr * 20 + c8;
    __half2 h0 = __floats2half2_rn(s[0], s[1]);
    __half2 h1 = __floats2half2_rn(s[2], s[3]);
    __half2 h2 = __floats2half2_rn(s[4], s[5]);
    __half2 h3 = __floats2half2_rn(s[6], s[7]);
    uint4 o;
    o.x = *(unsigned*)&h0; o.y = *(unsigned*)&h1;
    o.z = *(unsigned*)&h2; o.w = *(unsigned*)&h3;
    *(uint4*)(gdst + (size_t)rr * ldg + c8) = o;
}

// ---------------- 0. merged misc: setup + x->half + pool/softmax + v -------
// grid: [0,256) setup | [256,2304) xh | [2304,7168) poolsm | [7168,7244) v
__global__ void k_misc(const float* __restrict__ x, const float* __restrict__ sim,
                       const float* __restrict__ gcc,
                       const float* __restrict__ Wq, const float* __restrict__ Wk,
                       const float* __restrict__ Wc, const float* __restrict__ bq,
                       const float* __restrict__ Wv, const float* __restrict__ bv,
                       float* __restrict__ out_tail) {
    __shared__ float red[256];
    __shared__ float sg[512];
    int blk = blockIdx.x;
    int t = threadIdx.x;

    if (blk < 256) {
        int g = blk * 256 + t;
        int stride = 256 * 256;
        for (int i = g; i < Cc * MID; i += stride) {
            g_Wq_h[i] = __float2half(Wq[i]);
            g_Wk_h[i] = __float2half(Wk[i]);
            g_Wc_h[i] = __float2half(Wc[i]);
        }
        for (int i = g; i < 16 * MID; i += stride) g_qbias[i] = bq[i & (MID - 1)];
        for (int i = g; i < 64 * 4 * 1024; i += stride) {
            int bn = i >> 12, rem = i & 4095;
            g_smxh[((size_t)bn * 80 + 76) * 1024 + rem] = __float2half(0.f);
        }
        for (int i = g; i < 64 * 4 * 512; i += stride) {
            int bn = i >> 11, rem = i & 2047;
            g_localh[((size_t)bn * 80 + 76) * 512 + rem] = __float2half(0.f);
        }
    } else if (blk < 2304) {
        size_t n8 = (size_t)Bsz * Cc * HW / 8;
        size_t g = (size_t)(blk - 256) * 256 + t;
        size_t stride = (size_t)2048 * 256;
        for (; g < n8; g += stride) {
            const float4* s = (const float4*)x + g * 2;
            float4 a = s[0], b = s[1];
            __half2 h0 = __floats2half2_rn(a.x, a.y);
            __half2 h1 = __floats2half2_rn(a.z, a.w);
            __half2 h2 = __floats2half2_rn(b.x, b.y);
            __half2 h3 = __floats2half2_rn(b.z, b.w);
            uint4 o;
            o.x = *(unsigned*)&h0; o.y = *(unsigned*)&h1;
            o.z = *(unsigned*)&h2; o.w = *(unsigned*)&h3;
            ((uint4*)g_xh)[g] = o;
        }
    } else if (blk < 7168) {
        int id = blk - 2304;
        int cm = id % CMn;
        int bn = id / CMn;
        int n = bn & 15, b = bn >> 4;
        int i0 = (n >> 2) * 32, j0 = (n & 3) * 32;
        const float* base = sim + ((size_t)b * CMn + cm) * HW;
        float v[4];
        float mx = -1e30f, sraw = 0.f;
#pragma unroll
        for (int it = 0; it < 4; it++) {
            int p = t + it * 256;
            int pi = p >> 5, pj = p & 31;
            v[it] = base[(i0 + pi) * Ww + j0 + pj];
            mx = fmaxf(mx, v[it]);
            sraw += v[it];
        }
        red[t] = sraw; __syncthreads();
        for (int o = 128; o > 0; o >>= 1) {
            if (t < o) red[t] += red[t + o];
            __syncthreads();
        }
        if (t == 0) {
            float m = red[0] * (1.0f / 1024.0f);
            int pid = (b * CMn + cm) * 16 + n;
            g_pool[pid] = m;
            out_tail[pid] = m;
        }
        __syncthreads();
        red[t] = mx; __syncthreads();
        for (int o = 128; o > 0; o >>= 1) {
            if (t < o) red[t] = fmaxf(red[t], red[t + o]);
            __syncthreads();
        }
        float gmx = red[0]; __syncthreads();
        float s = 0.f;
#pragma unroll
        for (int it = 0; it < 4; it++) { v[it] = expf(v[it] - gmx); s += v[it]; }
        red[t] = s; __syncthreads();
        for (int o = 128; o > 0; o >>= 1) {
            if (t < o) red[t] += red[t + o];
            __syncthreads();
        }
        float inv = 1.0f / red[0];
        __half* dst = g_smxh + ((size_t)bn * 80 + cm) * Pp;
#pragma unroll
        for (int it = 0; it < 4; it++) { int p = t + it * 256; dst[p] = __float2half(v[it] * inv); }
    } else {
        int c = blk - 7168;
        for (int k = t; k < 512; k += 256) sg[k] = gcc[c * 512 + k];
        __syncthreads();
        float acc = 0.f;
        for (int k = 0; k < 512; k++) acc += sg[k] * Wv[k * MID + t];
        g_vvh[c * MID + t] = __float2half(acc + bv[t]);
    }
}

// ---------------- 3. local = smx^T @ xs * conf  (WMMA, cp.async x2) --------
__device__ __forceinline__ void local_stage(int tid, __half* Adst, __half* Bdst,
                                            const __half* Asrc, const __half* Bsrc,
                                            int it, int nBase, int baseoff) {
    for (int idx = tid; idx < 832; idx += 320) {
        if (idx < 320) {
            int row = idx >> 2, col = (idx & 3) * 8;
            cp16(Adst + row * 40 + col, Asrc + (size_t)row * 1024 + it * 32 + col);
        } else {
            int j = idx - 320;
            int row = j >> 2, col = (j & 3) * 8;
            cp16(Bdst + row * 40 + col,
                 Bsrc + (size_t)(nBase + row) * HW + baseoff + it * Ww + col);
        }
    }
    cp_commit();
}

__global__ __launch_bounds__(320, 2) void k_local_w() {
    __shared__ __align__(16) union {
        struct { __half A[2][80][40]; __half B[2][128][40]; } s;
        float C[80 * 136];
    } u;
    int bn = blockIdx.y;
    int b = bn >> 4, np = bn & 15;
    int i0 = (np >> 2) * 32, j0 = (np & 3) * 32;
    int baseoff = i0 * Ww + j0;
    int nBase = blockIdx.x * 128;
    const __half* Asrc = g_smxh + (size_t)bn * 80 * 1024;
    const __half* Bsrc = g_xh + (size_t)b * Cc * HW;
    int tid = threadIdx.x;
    int wid = tid >> 5;
    int wm = wid % 5, wn = wid / 5;

    wmma::fragment<wmma::accumulator, 16, 16, 16, float> c[4];
#pragma unroll
    for (int j = 0; j < 4; j++) wmma::fill_fragment(c[j], 0.f);

    local_stage(tid, &u.s.A[0][0][0], &u.s.B[0][0][0], Asrc, Bsrc, 0, nBase, baseoff);
    for (int it = 0; it < 32; it++) {
        if (it + 1 < 32) {
            int s2 = (it + 1) & 1;
            local_stage(tid, &u.s.A[s2][0][0], &u.s.B[s2][0][0], Asrc, Bsrc, it + 1, nBase, baseoff);
            cp_wait<1>();
        } else {
            cp_wait<0>();
        }
        __syncthreads();
        int s = it & 1;
#pragma unroll
        for (int ks = 0; ks < 32; ks += 16) {
            wmma::fragment<wmma::matrix_a, 16, 16, 16, __half, wmma::row_major> af;
            wmma::load_matrix_sync(af, &u.s.A[s][wm * 16][ks], 40);
#pragma unroll
            for (int j = 0; j < 4; j++) {
                wmma::fragment<wmma::matrix_b, 16, 16, 16, __half, wmma::col_major> bf;
                wmma::load_matrix_sync(bf, &u.s.B[s][wn * 64 + j * 16][ks], 40);
                wmma::mma_sync(c[j], af, bf, c[j]);
            }
        }
        __syncthreads();
    }
#pragma unroll
    for (int j = 0; j < 4; j++)
        wmma::store_matrix_sync(&u.C[(wm * 16) * 136 + wn * 64 + j * 16], c[j], 136,
                                wmma::mem_row_major);
    __syncthreads();
    for (int idx = tid; idx < 76 * 128; idx += 320) {
        int cc = idx >> 7, nn = idx & 127;
        float conf = g_pool[(b * CMn + cc) * 16 + np];
        g_localh[((size_t)bn * 80 + cc) * 512 + nBase + nn] =
            __float2half(u.C[cc * 136 + nn] * conf);
    }
}

// ---------------- 4. k = local @ Wk + bk (WMMA, half out) ----------------
__global__ __launch_bounds__(320, 2) void k_kproj_w(const float* __restrict__ bk) {
    __shared__ __align__(16) union {
        struct { __half A[80][40]; __half B[32][136]; } ab;
        float C[80 * 136];
    } u;
    int bn = blockIdx.y;
    int nBase = blockIdx.x * 128;
    const __half* Ap = g_localh + (size_t)bn * 80 * 512;
    int tid = threadIdx.x;
    int wid = tid >> 5;
    int wm = wid % 5, wn = wid / 5;

    wmma::fragment<wmma::accumulator, 16, 16, 16, float> c[4];
#pragma unroll
    for (int j = 0; j < 4; j++) wmma::fill_fragment(c[j], 0.f);

    for (int k0 = 0; k0 < 512; k0 += 32) {
        {
            int cc = tid >> 2;
            int h8 = (tid & 3) * 8;
            *(uint4*)&u.ab.A[cc][h8] = *(const uint4*)&Ap[(size_t)cc * 512 + k0 + h8];
        }
        for (int idx = tid; idx < 512; idx += 320) {
            int kk = idx >> 4;
            int nn = (idx & 15) * 8;
            *(uint4*)&u.ab.B[kk][nn] = *(const uint4*)&g_Wk_h[(k0 + kk) * MID + nBase + nn];
        }
        __syncthreads();
#pragma unroll
        for (int ks = 0; ks < 32; ks += 16) {
            wmma::fragment<wmma::matrix_a, 16, 16, 16, __half, wmma::row_major> af;
            wmma::load_matrix_sync(af, &u.ab.A[wm * 16][ks], 40);
#pragma unroll
            for (int j = 0; j < 4; j++) {
                wmma::fragment<wmma::matrix_b, 16, 16, 16, __half, wmma::row_major> bf;
                wmma::load_matrix_sync(bf, &u.ab.B[ks][wn * 64 + j * 16], 136);
                wmma::mma_sync(c[j], af, bf, c[j]);
            }
        }
        __syncthreads();
    }
#pragma unroll
    for (int j = 0; j < 4; j++)
        wmma::store_matrix_sync(&u.C[(wm * 16) * 136 + wn * 64 + j * 16], c[j], 136,
                                wmma::mem_row_major);
    __syncthreads();
    for (int idx = tid; idx < 76 * 128; idx += 320) {
        int cc = idx >> 7, nn = idx & 127;
        g_kkh[((size_t)bn * 76 + cc) * 256 + nBase + nn] =
            __float2half(u.C[cc * 136 + nn] + bk[nBase + nn]);
    }
}

// ---------------- 7. fused q-proj + attention (dynamic smem) ----------------
// grid (16 mtiles, 64 bn), 256 threads (8 warps).
// Q-phase warp grid: 2M x 4N (warp tile 32px x 64mid) — 33% fewer fragment loads.
// S/PV phases keep 4M x 2N decode.
#define ATTQ_SMEM 76800

__global__ __launch_bounds__(256, 2) void k_attq() {
    extern __shared__ __align__(16) char dyn[];
    __half* Qh = (__half*)dyn;                         // ld 264
    int bn = blockIdx.y;
    int b = bn >> 4, np = bn & 15;
    int i0 = (np >> 2) * 32, j0 = (np & 3) * 32;
    int mBase = blockIdx.x * 64;
    int tid = threadIdx.x;
    int lane = tid & 31;
    int wid = tid >> 5;
    const __half* xb = g_xh + (size_t)b * Cc * HW;

    // ===== phase Q: Q[64][256] = x^T @ Wq + bq  (warps: 2M x 4N) =====
    {
        int qm = wid & 1;          // 2 warps over 64 px (32 each)
        int qn = wid >> 1;         // 4 warps over 256 mid (64 each)
        wmma::fragment<wmma::accumulator, 16, 16, 16, float> c[2][4];
#pragma unroll
        for (int i = 0; i < 2; i++)
#pragma unroll
            for (int j = 0; j < 4; j++)
                wmma::load_matrix_sync(c[i][j], g_qbias + qn * 64 + j * 16, MID,
                                       wmma::mem_row_major);

        auto stage = [&](int s, int k0) {
#pragma unroll
            for (int l = 0; l < 5; l++) {
                int idx = tid + l * 256;
                char* base = dyn + 33792 + s * 21504;
                if (idx < 256) {
                    int ch = idx >> 3;
                    int px = (idx & 7) * 8;
                    int p = mBase + px;
                    cp16((__half*)base + ch * 72 + px,
                         xb + (size_t)(k0 + ch) * HW + (i0 + (p >> 5)) * 128 + j0 + (p & 31));
                } else {
                    int j = idx - 256;
                    int kk = j >> 5;
                    int n = (j & 31) * 8;
                    cp16((__half*)(base + 4608) + kk * 264 + n,
                         g_Wq_h + (k0 + kk) * MID + n);
                }
            }
            cp_commit();
        };

        stage(0, 0);
        for (int it = 0; it < 16; it++) {
            if (it + 1 < 16) {
                stage((it + 1) & 1, (it + 1) * 32);
                cp_wait<1>();
            } else {
                cp_wait<0>();
            }
            __syncthreads();
            int s = it & 1;
            __half* As = (__half*)(dyn + 33792 + s * 21504);
            __half* Bs = (__half*)(dyn + 33792 + s * 21504 + 4608);
#pragma unroll
            for (int ks = 0; ks < 32; ks += 16) {
                wmma::fragment<wmma::matrix_a, 16, 16, 16, __half, wmma::col_major> af[2];
                wmma::fragment<wmma::matrix_b, 16, 16, 16, __half, wmma::row_major> bf[4];
#pragma unroll
                for (int i = 0; i < 2; i++)
                    wmma::load_matrix_sync(af[i], As + ks * 72 + qm * 32 + i * 16, 72);
#pragma unroll
                for (int j = 0; j < 4; j++)
                    wmma::load_matrix_sync(bf[j], Bs + ks * 264 + qn * 64 + j * 16, 264);
#pragma unroll
                for (int i = 0; i < 2; i++)
#pragma unroll
                    for (int j = 0; j < 4; j++)
                        wmma::mma_sync(c[i][j], af[i], bf[j], c[i][j]);
            }
            __syncthreads();
        }
        // write Q (half) into Qh via per-warp scratch
        float* scr = (float*)(dyn + 33792) + wid * 320;   // [16][20]
#pragma unroll
        for (int i = 0; i < 2; i++)
#pragma unroll
            for (int j = 0; j < 4; j++) {
                wmma::store_matrix_sync(scr, c[i][j], 20, wmma::mem_row_major);
                __syncwarp();
                scr_to_half(scr, Qh + (qm * 32 + i * 16) * 264 + qn * 64 + j * 16, 264, lane);
                __syncwarp();
            }
    }
    __syncthreads();

    // ===== phase S: S = Q @ K^T  (warps: 4M x 2N) =====
    int wm = wid & 3;
    int wn = wid >> 2;
    __half* Ksm = (__half*)(dyn + 33792);                // [80][72]
    float*  Sf  = (float*)(dyn + 45312);                 // [64][92]
    const __half* ksrc = g_kkh + (size_t)bn * 76 * 256;
    int nfr = (wn == 0) ? 3 : 2;
    int nb0 = (wn == 0) ? 0 : 48;
    {
        wmma::fragment<wmma::accumulator, 16, 16, 16, float> sacc[3];
#pragma unroll
        for (int f = 0; f < 3; f++) wmma::fill_fragment(sacc[f], 0.f);

        for (int k0 = 0; k0 < 256; k0 += 64) {
            for (int idx = tid; idx < 640; idx += 256) {
                int row = idx >> 3, c8 = (idx & 7) * 8;
                uint4 z = {0, 0, 0, 0};
                uint4 val = (row < 76) ? *(const uint4*)&ksrc[(size_t)row * 256 + k0 + c8] : z;
                *(uint4*)(Ksm + row * 72 + c8) = val;
            }
            __syncthreads();
#pragma unroll
            for (int ks = 0; ks < 64; ks += 16) {
                wmma::fragment<wmma::matrix_a, 16, 16, 16, __half, wmma::row_major> af;
                wmma::load_matrix_sync(af, Qh + (wm * 16) * 264 + k0 + ks, 264);
                for (int f = 0; f < nfr; f++) {
                    wmma::fragment<wmma::matrix_b, 16, 16, 16, __half, wmma::col_major> bf;
                    wmma::load_matrix_sync(bf, Ksm + (nb0 + f * 16) * 72 + ks, 72);
                    wmma::mma_sync(sacc[f], af, bf, sacc[f]);
                }
            }
            __syncthreads();
        }
        for (int f = 0; f < nfr; f++)
            wmma::store_matrix_sync(Sf + (wm * 16) * 92 + nb0 + f * 16, sacc[f], 92,
                                    wmma::mem_row_major);
    }
    __syncthreads();

    // ===== softmax -> P (half, overlays Qh region) =====
    __half* P = (__half*)dyn;                            // [64][88]
    if (tid < 64) {
        const float* srow = Sf + tid * 92;
        float mx = -1e30f;
        for (int c = 0; c < 76; c++) mx = fmaxf(mx, srow[c]);
        float s = 0.f;
        float e[76];
        for (int c = 0; c < 76; c++) { e[c] = expf(srow[c] - mx); s += e[c]; }
        float inv = 1.0f / s;
        __half* prow = P + tid * 88;
        for (int c = 0; c < 76; c++) prow[c] = __float2half(e[c] * inv);
        prow[76] = __float2half(0.f);
        prow[77] = __float2half(0.f);
        prow[78] = __float2half(0.f);
        prow[79] = __float2half(0.f);
    }
    __syncthreads();

    // ===== phase PV: O = P @ V =====
    __half* Vsm = (__half*)(dyn + 33792);                // [80][136]
    float* scr2 = (float*)(dyn + 55552) + wid * 320;     // [16][20] per warp
    for (int hb = 0; hb < 2; hb++) {
        for (int idx = tid; idx < 1280; idx += 256) {
            int row = idx >> 4, c8 = (idx & 15) * 8;
            uint4 z = {0, 0, 0, 0};
            uint4 val = (row < 76) ? *(const uint4*)&g_vvh[row * 256 + hb * 128 + c8] : z;
            *(uint4*)(Vsm + row * 136 + c8) = val;
        }
        __syncthreads();
        wmma::fragment<wmma::accumulator, 16, 16, 16, float> oacc[4];
#pragma unroll
        for (int j = 0; j < 4; j++) wmma::fill_fragment(oacc[j], 0.f);
#pragma unroll
        for (int kc = 0; kc < 5; kc++) {
            int ks = kc * 16;
            wmma::fragment<wmma::matrix_a, 16, 16, 16, __half, wmma::row_major> pf;
            wmma::load_matrix_sync(pf, P + (wm * 16) * 88 + ks, 88);
#pragma unroll
            for (int j = 0; j < 4; j++) {
                wmma::fragment<wmma::matrix_b, 16, 16, 16, __half, wmma::row_major> vf;
                wmma::load_matrix_sync(vf, Vsm + ks * 136 + wn * 64 + j * 16, 136);
                wmma::mma_sync(oacc[j], pf, vf, oacc[j]);
            }
        }
        __half* obase = g_oh + ((size_t)bn * 1024 + mBase + wm * 16) * 256 + hb * 128 + wn * 64;
#pragma unroll
        for (int j = 0; j < 4; j++) {
            wmma::store_matrix_sync(scr2, oacc[j], 20, wmma::mem_row_major);
            __syncwarp();
            scr_to_half(scr2, obase + j * 16, 256, lane);
            __syncwarp();
        }
        __syncthreads();
    }
}

// ---------------- 8. conv (WMMA) + BN + ReLU, patch-major A ----------------
__global__ __launch_bounds__(256, 2) void k_conv_w(const float* __restrict__ gamma,
                                                   const float* __restrict__ beta,
                                                   const float* __restrict__ mean,
                                                   const float* __restrict__ var,
                                                   float* __restrict__ y) {
    __shared__ __align__(16) union {
        struct { __half A[128][40]; __half B[32][72]; } ab;
        float C[64 * 136];
    } u;
    int nBase = blockIdx.x * 64;
    int mBase = blockIdx.y * 128;
    int tid = threadIdx.x;
    int wid = tid >> 5;
    int wm = wid & 3;
    int wn = wid >> 2;

    wmma::fragment<wmma::accumulator, 16, 16, 16, float> c[2][2];
#pragma unroll
    for (int i = 0; i < 2; i++)
#pragma unroll
        for (int j = 0; j < 2; j++) wmma::fill_fragment(c[i][j], 0.f);

    for (int k0 = 0; k0 < 256; k0 += 32) {
#pragma unroll
        for (int l = 0; l < 2; l++) {
            int idx = tid + l * 256;
            int m = idx >> 2;
            int k8 = (idx & 3) * 8;
            *(uint4*)&u.ab.A[m][k8] = *(const uint4*)&g_oh[(size_t)(mBase + m) * 256 + k0 + k8];
        }
        {
            int kk = tid >> 3;
            int n = (tid & 7) * 8;
            *(uint4*)&u.ab.B[kk][n] = *(const uint4*)&g_Wc_h[(k0 + kk) * Cc + nBase + n];
        }
        __syncthreads();
#pragma unroll
        for (int ks = 0; ks < 32; ks += 16) {
            wmma::fragment<wmma::matrix_a, 16, 16, 16, __half, wmma::row_major> af[2];
            wmma::fragment<wmma::matrix_b, 16, 16, 16, __half, wmma::row_major> bf[2];
#pragma unroll
            for (int i = 0; i < 2; i++)
                wmma::load_matrix_sync(af[i], &u.ab.A[wm * 32 + i * 16][ks], 40);
#pragma unroll
            for (int j = 0; j < 2; j++)
                wmma::load_matrix_sync(bf[j], &u.ab.B[ks][wn * 32 + j * 16], 72);
#pragma unroll
            for (int i = 0; i < 2; i++)
#pragma unroll
                for (int j = 0; j < 2; j++)
                    wmma::mma_sync(c[i][j], af[i], bf[j], c[i][j]);
        }
        __syncthreads();
    }

#pragma unroll
    for (int i = 0; i < 2; i++)
#pragma unroll
        for (int j = 0; j < 2; j++)
            wmma::store_matrix_sync(&u.C[(wn * 32 + j * 16) * 136 + wm * 32 + i * 16],
                                    c[i][j], 136, wmma::mem_col_major);
    __syncthreads();

    {
        int n = tid >> 2;
        int q4 = tid & 3;
        int ch = nBase + n;
        float iv = gamma[ch] / sqrtf(var[ch] + 1e-5f);
        float ad = beta[ch] - mean[ch] * iv;
        int bn = mBase >> 10;
        int pp0 = mBase & 1023;
        int b = bn >> 4, np = bn & 15;
        int i0 = (np >> 2) * 32, j0 = (np & 3) * 32;
        float* ybase = y + ((size_t)b * Cc + ch) * HW;
        const float* crow = &u.C[n * 136];
#pragma unroll
        for (int l = 0; l < 8; l++) {
            int m = (q4 + l * 4) * 4;
            int p = pp0 + m;
            float4 v = *(const float4*)&crow[m];
            v.x = fmaxf(v.x * iv + ad, 0.f);
            v.y = fmaxf(v.y * iv + ad, 0.f);
            v.z = fmaxf(v.z * iv + ad, 0.f);
            v.w = fmaxf(v.w * iv + ad, 0.f);
            *(float4*)&ybase[(i0 + (p >> 5)) * 128 + j0 + (p & 31)] = v;
        }
    }
}

// ---------------- launcher ----------------
extern "C" void kernel_launch(void* const* d_in, const int* in_sizes, int n_in,
                              void* d_out, int out_size) {
    const float* x   = (const float*)d_in[0];
    const float* sim = (const float*)d_in[1];
    const float* gcc = (const float*)d_in[2];
    const float* Wq  = (const float*)d_in[3];
    const float* bq  = (const float*)d_in[4];
    const float* Wk  = (const float*)d_in[5];
    const float* bk  = (const float*)d_in[6];
    const float* Wv  = (const float*)d_in[7];
    const float* bv  = (const float*)d_in[8];
    const float* Wc  = (const float*)d_in[9];
    const float* gm  = (const float*)d_in[10];
    const float* bt  = (const float*)d_in[11];
    const float* mn  = (const float*)d_in[12];
    const float* vr  = (const float*)d_in[13];
    float* y = (float*)d_out;
    float* tail = y + (size_t)Bsz * Cc * HW;

    cudaFuncSetAttribute(k_attq, cudaFuncAttributeMaxDynamicSharedMemorySize, ATTQ_SMEM);

    k_misc<<<7244, 256>>>(x, sim, gcc, Wq, Wk, Wc, bq, Wv, bv, tail);
    k_local_w<<<dim3(4, 64), 320>>>();
    k_kproj_w<<<dim3(2, 64), 320>>>(bk);
    k_attq<<<dim3(16, 64), 256, ATTQ_SMEM>>>();
    k_conv_w<<<dim3(8, 512), 256>>>(gm, bt, mn, vr, y);
}